// round 13
// baseline (speedup 1.0000x reference)
#include <cuda_runtime.h>
#include <cuda_bf16.h>
#include <stdint.h>
#include <math.h>

#define BB 2
#define SS 2048
#define DD 1024
#define HH 16
#define HD 64
#define NEG_INF (__int_as_float(0xff800000))

// ---------------- device scratch ----------------
__device__ __nv_bfloat16 xh_d[BB*SS*DD], xl_d[BB*SS*DD];
__device__ __nv_bfloat16 Wqh_d[DD*DD], Wql_d[DD*DD];
__device__ __nv_bfloat16 Wkh_d[DD*DD], Wkl_d[DD*DD];
__device__ __nv_bfloat16 Wvh_d[DD*DD], Wvl_d[DD*DD];
__device__ __nv_bfloat16 Woh_d[DD*DD], Wol_d[DD*DD];
__device__ float qf_d[BB*HH*SS*HD], kf_d[BB*HH*SS*HD], vf_d[BB*HH*SS*HD];
__device__ __nv_bfloat16 qh_d[BB*HH*SS*HD], ql_d[BB*HH*SS*HD];
__device__ __nv_bfloat16 kh_d[BB*HH*SS*HD], kl_d[BB*HH*SS*HD];
__device__ __nv_bfloat16 vth_d[BB*HH*SS*HD], vtl_d[BB*HH*SS*HD];
__device__ __nv_bfloat16 oh_d[BB*SS*DD], ol_d[BB*SS*DD];

// ---------------- helpers ----------------
__device__ __forceinline__ uint32_t smem_u32(const void* p) {
    uint32_t a;
    asm("{ .reg .u64 t; cvta.to.shared.u64 t, %1; cvt.u32.u64 %0, t; }" : "=r"(a) : "l"(p));
    return a;
}
#define SWZ(x) ((x) ^ (((x) >> 3) & 0x70))

__device__ __forceinline__ void cpa16(uint32_t dst, const void* src) {
    asm volatile("cp.async.cg.shared.global [%0], [%1], 16;" :: "r"(dst), "l"(src));
}
#define CP_COMMIT() asm volatile("cp.async.commit_group;" ::: "memory")
#define CP_WAIT1()  asm volatile("cp.async.wait_group 1;" ::: "memory")
#define CP_WAIT0()  asm volatile("cp.async.wait_group 0;" ::: "memory")

__device__ __forceinline__ void ldm4(uint32_t r[4], uint32_t a) {
    asm volatile("ldmatrix.sync.aligned.m8n8.x4.shared.b16 {%0,%1,%2,%3}, [%4];"
        : "=r"(r[0]), "=r"(r[1]), "=r"(r[2]), "=r"(r[3]) : "r"(a));
}
__device__ __forceinline__ void mma_bf16(float* c, const uint32_t* a, const uint32_t* b) {
    asm volatile("mma.sync.aligned.m16n8k16.row.col.f32.bf16.bf16.f32 "
        "{%0,%1,%2,%3}, {%4,%5,%6,%7}, {%8,%9}, {%0,%1,%2,%3};"
        : "+f"(c[0]), "+f"(c[1]), "+f"(c[2]), "+f"(c[3])
        : "r"(a[0]), "r"(a[1]), "r"(a[2]), "r"(a[3]), "r"(b[0]), "r"(b[1]));
}
__device__ __forceinline__ uint32_t pk2(float a, float b) {
    __nv_bfloat162 t = __floats2bfloat162_rn(a, b);
    return *(uint32_t*)&t;
}
__device__ __forceinline__ float bfh(float v) {
    return __bfloat162float(__float2bfloat16_rn(v));
}
__device__ __forceinline__ void split1(float v, __nv_bfloat16& h, __nv_bfloat16& l) {
    h = __float2bfloat16_rn(v);
    l = __float2bfloat16_rn(v - __bfloat162float(h));
}

// ---------------- merged split kernel ----------------
struct SplitArgs {
    const float* in[5];
    __nv_bfloat16* oh[5];
    __nv_bfloat16* ol[5];
    int n4[5];
};
__global__ void split_kernel(SplitArgs a) {
    int w = blockIdx.y;
    int i = blockIdx.x * blockDim.x + threadIdx.x;
    if (i >= a.n4[w]) return;
    float4 v = ((const float4*)a.in[w])[i];
    uint2 hv, lv;
    hv.x = pk2(v.x, v.y); hv.y = pk2(v.z, v.w);
    lv.x = pk2(v.x - bfh(v.x), v.y - bfh(v.y));
    lv.y = pk2(v.z - bfh(v.z), v.w - bfh(v.w));
    ((uint2*)a.oh[w])[i] = hv;
    ((uint2*)a.ol[w])[i] = lv;
}

// ---------------- split-bf16 HMMA GEMM core ----------------
// CTA tile 256x128, K-chunk 64, 256 thr, 8 warps as 4m x 2n, warp tile 64x64.
// stage (98304B): AH 0 (32K), AL 32768 (32K), BH 65536 (16K), BL 81920 (16K)
#define G_STG 98304
#define G_SMEM 196608

__device__ __forceinline__ void gemm_core(
    uint32_t sb, int tid, int m0, int n0,
    const __nv_bfloat16* __restrict__ Ah, const __nv_bfloat16* __restrict__ Al,
    const __nv_bfloat16* __restrict__ Bh, const __nv_bfloat16* __restrict__ Bl,
    float acc[4][8][4])
{
    const int wid = tid >> 5, l = tid & 31;
    const int wm = wid & 3, wn = wid >> 2;

    auto load_stage = [&](int c, int buf) {
        const int kt = c * 64;
        const uint32_t so = sb + buf * G_STG;
        #pragma unroll
        for (int t = 0; t < 8; ++t) {                 // A: 256 rows
            int e = tid + t * 256;
            int row = e >> 3, u = e & 7;
            uint32_t dst = SWZ((uint32_t)(row * 128 + u * 16));
            size_t ga = (size_t)(m0 + row) * DD + kt + u * 8;
            cpa16(so + dst,         Ah + ga);
            cpa16(so + 32768 + dst, Al + ga);
        }
        #pragma unroll
        for (int t = 0; t < 4; ++t) {                 // B: 128 rows
            int e = tid + t * 256;
            int row = e >> 3, u = e & 7;
            uint32_t dst = SWZ((uint32_t)(row * 128 + u * 16));
            size_t gb = (size_t)(n0 + row) * DD + kt + u * 8;
            cpa16(so + 65536 + dst, Bh + gb);
            cpa16(so + 81920 + dst, Bl + gb);
        }
    };

    load_stage(0, 0); CP_COMMIT();

    for (int c = 0; c < 16; ++c) {
        if (c < 15) { load_stage(c + 1, (c + 1) & 1); CP_COMMIT(); CP_WAIT1(); }
        else        { CP_WAIT0(); }
        __syncthreads();
        const uint32_t so = sb + (c & 1) * G_STG;
        #pragma unroll
        for (int ks = 0; ks < 4; ++ks) {
            uint32_t bh4[4][4], bl4[4][4];
            #pragma unroll
            for (int np = 0; np < 4; ++np) {
                int row = wn * 64 + np * 16 + ((l >> 4) & 1) * 8 + (l & 7);
                uint32_t off = SWZ((uint32_t)(row * 128 + ks * 32 + ((l >> 3) & 1) * 16));
                ldm4(bh4[np], so + 65536 + off);
                ldm4(bl4[np], so + 81920 + off);
            }
            #pragma unroll
            for (int mt = 0; mt < 4; ++mt) {
                int row = wm * 64 + mt * 16 + (l & 7) + ((l >> 3) & 1) * 8;
                uint32_t off = SWZ((uint32_t)(row * 128 + ks * 32 + ((l >> 4) & 1) * 16));
                uint32_t ah4[4], al4[4];
                ldm4(ah4, so + off);
                ldm4(al4, so + 32768 + off);
                #pragma unroll
                for (int nt = 0; nt < 8; ++nt) {
                    const uint32_t* bh = &bh4[nt >> 1][(nt & 1) * 2];
                    const uint32_t* bl = &bl4[nt >> 1][(nt & 1) * 2];
                    mma_bf16(acc[mt][nt], ah4, bh);
                    mma_bf16(acc[mt][nt], al4, bh);
                    mma_bf16(acc[mt][nt], ah4, bl);
                }
            }
        }
        __syncthreads();
    }
}

template<bool HEAD>
__device__ __forceinline__ void gemm_epilogue(
    int tid, int m0, int n0, const float* __restrict__ bias, float scale,
    float* __restrict__ C, float acc[4][8][4])
{
    const int wid = tid >> 5, l = tid & 31;
    const int wm = wid & 3, wn = wid >> 2;
    #pragma unroll
    for (int mt = 0; mt < 4; ++mt) {
        #pragma unroll
        for (int nt = 0; nt < 8; ++nt) {
            const float* cc = acc[mt][nt];
            int col = n0 + wn * 64 + nt * 8 + 2 * (l & 3);
            float b0 = bias ? bias[col] : 0.f;
            float b1 = bias ? bias[col + 1] : 0.f;
            int r0 = m0 + wm * 64 + mt * 16 + (l >> 2);
            #pragma unroll
            for (int hh = 0; hh < 2; ++hh) {
                int r = r0 + hh * 8;
                float2 w = {(cc[hh*2] + b0) * scale, (cc[hh*2+1] + b1) * scale};
                if (HEAD) {
                    int bb = r >> 11, s = r & (SS - 1);
                    int h = col >> 6, d = col & 63;
                    *(float2*)(C + (((size_t)(bb * HH + h)) * SS + s) * HD + d) = w;
                } else {
                    *(float2*)(C + (size_t)r * DD + col) = w;
                }
            }
        }
    }
}

// fused QKV projection: grid (24, 16); blockIdx.x>>3 selects Q/K/V
__global__ __launch_bounds__(256, 1)
void qkv_gemm(const __nv_bfloat16* __restrict__ Ah, const __nv_bfloat16* __restrict__ Al,
              const __nv_bfloat16* __restrict__ Qh, const __nv_bfloat16* __restrict__ Ql,
              const __nv_bfloat16* __restrict__ Kh, const __nv_bfloat16* __restrict__ Kl,
              const __nv_bfloat16* __restrict__ Vh, const __nv_bfloat16* __restrict__ Vl,
              const float* __restrict__ bq, const float* __restrict__ bv,
              float* __restrict__ qf, float* __restrict__ kf, float* __restrict__ vf)
{
    extern __shared__ char sm[];
    const uint32_t sb = smem_u32(sm);
    const int tid = threadIdx.x;
    const int which = blockIdx.x >> 3;
    const int n0 = (blockIdx.x & 7) * 128;
    const int m0 = blockIdx.y * 256;
    const float SC = 0.35355339059327373f;

    const __nv_bfloat16* Bh = (which == 0) ? Qh : (which == 1) ? Kh : Vh;
    const __nv_bfloat16* Bl = (which == 0) ? Ql : (which == 1) ? Kl : Vl;
    const float* bias = (which == 0) ? bq : (which == 1) ? (const float*)0 : bv;
    float scale = (which == 2) ? 1.f : SC;
    float* C = (which == 0) ? qf : (which == 1) ? kf : vf;

    float acc[4][8][4] = {};
    gemm_core(sb, tid, m0, n0, Ah, Al, Bh, Bl, acc);
    gemm_epilogue<true>(tid, m0, n0, bias, scale, C, acc);
}

// output projection: grid (8, 16)
__global__ __launch_bounds__(256, 1)
void out_gemm(const __nv_bfloat16* __restrict__ Ah, const __nv_bfloat16* __restrict__ Al,
              const __nv_bfloat16* __restrict__ Bh, const __nv_bfloat16* __restrict__ Bl,
              const float* __restrict__ bias, float* __restrict__ C)
{
    extern __shared__ char sm[];
    const uint32_t sb = smem_u32(sm);
    const int tid = threadIdx.x;
    const int n0 = blockIdx.x * 128, m0 = blockIdx.y * 256;
    float acc[4][8][4] = {};
    gemm_core(sb, tid, m0, n0, Ah, Al, Bh, Bl, acc);
    gemm_epilogue<false>(tid, m0, n0, bias, 1.f, C, acc);
}

// ---------------- RoPE + split ----------------
__global__ void rope_kernel(const float* __restrict__ q, const float* __restrict__ k,
                            const int* __restrict__ pos,
                            __nv_bfloat16* __restrict__ qh, __nv_bfloat16* __restrict__ ql,
                            __nv_bfloat16* __restrict__ kh, __nv_bfloat16* __restrict__ kl)
{
    int idx = blockIdx.x * blockDim.x + threadIdx.x;
    if (idx >= BB * HH * SS * 32) return;
    int j = idx & 31;
    int s = (idx >> 5) & (SS - 1);
    int bh = idx >> 16;
    int b = bh >> 4;

    int p = pos[b * SS + s];
    float inv = expf(-(float)(2 * j) * (9.210340371976184f / 64.f));
    float ang = (float)p * inv;
    float sn, cs;
    sincosf(ang, &sn, &cs);

    size_t base = (size_t)bh * SS * HD + (size_t)s * HD + j;
    float q1 = q[base], q2 = q[base + 32];
    float k1 = k[base], k2 = k[base + 32];
    float qa = q1 * cs - q2 * sn, qb2 = q2 * cs + q1 * sn;
    float ka = k1 * cs - k2 * sn, kb2 = k2 * cs + k1 * sn;
    __nv_bfloat16 h, l;
    split1(qa, h, l);  qh[base] = h;      ql[base] = l;
    split1(qb2, h, l); qh[base + 32] = h; ql[base + 32] = l;
    split1(ka, h, l);  kh[base] = h;      kl[base] = l;
    split1(kb2, h, l); kh[base + 32] = h; kl[base + 32] = l;
}

// ---------------- V transpose + split ----------------
__global__ __launch_bounds__(256)
void vtrans_kernel(const float* __restrict__ v,
                   __nv_bfloat16* __restrict__ vth, __nv_bfloat16* __restrict__ vtl)
{
    __shared__ float ts[64][65];
    const int tid = threadIdx.x;
    const int s0 = blockIdx.x * 64;
    const int bh = blockIdx.y;
    #pragma unroll
    for (int t = 0; t < 16; ++t) {
        int e = tid + t * 256;
        int row = e >> 6, col = e & 63;
        ts[row][col] = v[((size_t)bh * SS + s0 + row) * HD + col];
    }
    __syncthreads();
    #pragma unroll
    for (int t = 0; t < 16; ++t) {
        int e = tid + t * 256;
        int d = e >> 6, s = e & 63;
        __nv_bfloat16 h, l;
        split1(ts[s][d], h, l);
        size_t a = ((size_t)bh * HD + d) * SS + s0 + s;
        vth[a] = h;
        vtl[a] = l;
    }
}

// ---------------- attention, 2-stage cp.async pipeline (R11 config) ----------------
#define A_QH   0
#define A_QL   16384
#define A_ST   32768
#define A_STG  32768
#define A_ORED 32768
#define A_MK   98304
#define A_LRED 98816
#define A_SMEM 99840

__global__ __launch_bounds__(256, 2)
void attn_kernel(const __nv_bfloat16* __restrict__ qh, const __nv_bfloat16* __restrict__ ql,
                 const __nv_bfloat16* __restrict__ kh, const __nv_bfloat16* __restrict__ kl,
                 const __nv_bfloat16* __restrict__ vth, const __nv_bfloat16* __restrict__ vtl,
                 const int* __restrict__ mask,
                 float* __restrict__ qk_out,
                 __nv_bfloat16* __restrict__ ohp, __nv_bfloat16* __restrict__ olp)
{
    extern __shared__ char sm[];
    const uint32_t sb = smem_u32(sm);
    const int tid = threadIdx.x, wid = tid >> 5, l = tid & 31;
    const int wm = wid & 3, wn = wid >> 2;
    const int qb = blockIdx.x;
    const int bh = blockIdx.y;
    const int b = bh >> 4, h = bh & 15;
    int* mki = (int*)(sm + A_MK);
    float* lred = (float*)(sm + A_LRED);
    float* ored = (float*)(sm + A_ORED);

    #pragma unroll
    for (int t = 0; t < 4; ++t) {
        int e = tid + t * 256;
        int row = e >> 3, u = e & 7;
        uint32_t dst = SWZ((uint32_t)(row * 128 + u * 16));
        size_t src = ((size_t)bh * SS + qb * 128 + row) * HD + u * 8;
        *(uint4*)(sm + A_QH + dst) = *(const uint4*)(qh + src);
        *(uint4*)(sm + A_QL + dst) = *(const uint4*)(ql + src);
    }

    const int* mp = mask + b * SS;
    float* qkb = qk_out ? qk_out + ((size_t)bh * SS + (size_t)qb * 128) * SS : (float*)0;

    auto load_kv = [&](int kt, int buf) {
        const uint32_t so = sb + A_ST + buf * A_STG;
        #pragma unroll
        for (int t = 0; t < 2; ++t) {
            int e = tid + t * 256;
            int row = e >> 3, u = e & 7;
            uint32_t dst = SWZ((uint32_t)(row * 128 + u * 16));
            size_t ks = ((size_t)bh * SS + kt * 64 + row) * HD + u * 8;
            size_t vs = ((size_t)bh * HD + row) * SS + kt * 64 + u * 8;
            cpa16(so + dst,         kh  + ks);
            cpa16(so + 8192 + dst,  kl  + ks);
            cpa16(so + 16384 + dst, vth + vs);
            cpa16(so + 24576 + dst, vtl + vs);
        }
        if (tid < 16) cpa16(sb + A_MK + buf * 256 + tid * 16, mp + kt * 64 + tid * 4);
    };

    float oacc[2][8][4] = {};
    float lsum[2][2] = {};

    load_kv(0, 0);
    CP_COMMIT();

    for (int kt = 0; kt < 32; ++kt) {
        if (kt < 31) { load_kv(kt + 1, (kt + 1) & 1); CP_COMMIT(); CP_WAIT1(); }
        else         { CP_WAIT0(); }
        __syncthreads();
        const uint32_t so = sb + A_ST + (kt & 1) * A_STG;
        const int* mk = mki + (kt & 1) * 64;

        float sacc[2][4][4] = {};
        #pragma unroll
        for (int ks = 0; ks < 4; ++ks) {
            uint32_t kh4[2][4], kl4[2][4];
            #pragma unroll
            for (int np = 0; np < 2; ++np) {
                int row = wn * 32 + np * 16 + ((l >> 4) & 1) * 8 + (l & 7);
                uint32_t off = SWZ((uint32_t)(row * 128 + ks * 32 + ((l >> 3) & 1) * 16));
                ldm4(kh4[np], so + off);
                ldm4(kl4[np], so + 8192 + off);
            }
            #pragma unroll
            for (int mt = 0; mt < 2; ++mt) {
                int row = wm * 32 + mt * 16 + (l & 7) + ((l >> 3) & 1) * 8;
                uint32_t off = SWZ((uint32_t)(row * 128 + ks * 32 + ((l >> 4) & 1) * 16));
                uint32_t qh4[4], ql4[4];
                ldm4(qh4, sb + A_QH + off);
                ldm4(ql4, sb + A_QL + off);
                #pragma unroll
                for (int nt = 0; nt < 4; ++nt) {
                    const uint32_t* bhf = &kh4[nt >> 1][(nt & 1) * 2];
                    const uint32_t* blf = &kl4[nt >> 1][(nt & 1) * 2];
                    mma_bf16(sacc[mt][nt], qh4, bhf);
                    mma_bf16(sacc[mt][nt], ql4, bhf);
                    mma_bf16(sacc[mt][nt], qh4, blf);
                }
            }
        }

        uint32_t ph[2][2][4], pl[2][2][4];
        #pragma unroll
        for (int mt = 0; mt < 2; ++mt) {
            #pragma unroll
            for (int nt = 0; nt < 4; ++nt) {
                float* cc = sacc[mt][nt];
                int colg = wn * 32 + nt * 8 + 2 * (l & 3);
                int mv0 = mk[colg], mv1 = mk[colg + 1];
                int r0 = wm * 32 + mt * 16 + (l >> 2);
                if (qkb) {
                    float2 w0 = {mv0 ? cc[0] : NEG_INF, mv1 ? cc[1] : NEG_INF};
                    float2 w1 = {mv0 ? cc[2] : NEG_INF, mv1 ? cc[3] : NEG_INF};
                    __stcs((float2*)(qkb + (size_t)r0 * SS + kt * 64 + colg), w0);
                    __stcs((float2*)(qkb + (size_t)(r0 + 8) * SS + kt * 64 + colg), w1);
                }
                float p0 = mv0 ? __expf(cc[0]) : 0.f;
                float p1 = mv1 ? __expf(cc[1]) : 0.f;
                float p2 = mv0 ? __expf(cc[2]) : 0.f;
                float p3 = mv1 ? __expf(cc[3]) : 0.f;
                lsum[mt][0] += p0 + p1;
                lsum[mt][1] += p2 + p3;
                int t2 = nt >> 1, pos = nt & 1;
                ph[mt][t2][pos * 2]     = pk2(p0, p1);
                ph[mt][t2][pos * 2 + 1] = pk2(p2, p3);
                pl[mt][t2][pos * 2]     = pk2(p0 - bfh(p0), p1 - bfh(p1));
                pl[mt][t2][pos * 2 + 1] = pk2(p2 - bfh(p2), p3 - bfh(p3));
            }
        }

        #pragma unroll
        for (int ks = 0; ks < 2; ++ks) {
            #pragma unroll
            for (int dp = 0; dp < 4; ++dp) {
                int row = dp * 16 + ((l >> 4) & 1) * 8 + (l & 7);
                uint32_t off = SWZ((uint32_t)(row * 128 + wn * 64 + ks * 32 + ((l >> 3) & 1) * 16));
                uint32_t vh4[4], vl4[4];
                ldm4(vh4, so + 16384 + off);
                ldm4(vl4, so + 24576 + off);
                #pragma unroll
                for (int mt = 0; mt < 2; ++mt) {
                    #pragma unroll
                    for (int q2 = 0; q2 < 2; ++q2) {
                        float* o = oacc[mt][dp * 2 + q2];
                        const uint32_t* bhf = &vh4[q2 * 2];
                        const uint32_t* blf = &vl4[q2 * 2];
                        mma_bf16(o, ph[mt][ks], bhf);
                        mma_bf16(o, pl[mt][ks], bhf);
                        mma_bf16(o, ph[mt][ks], blf);
                    }
                }
            }
        }
        __syncthreads();
    }

    #pragma unroll
    for (int mt = 0; mt < 2; ++mt) {
        #pragma unroll
        for (int hf = 0; hf < 2; ++hf) {
            float v = lsum[mt][hf];
            v += __shfl_xor_sync(0xffffffffu, v, 1);
            v += __shfl_xor_sync(0xffffffffu, v, 2);
            int row = wm * 32 + mt * 16 + hf * 8 + (l >> 2);
            if ((l & 3) == 0) lred[wn * 128 + row] = v;
        }
    }
    if (wn == 0) {
        #pragma unroll
        for (int mt = 0; mt < 2; ++mt) {
            #pragma unroll
            for (int dt = 0; dt < 8; ++dt) {
                const float* o = oacc[mt][dt];
                int col = dt * 8 + 2 * (l & 3);
                int r0 = wm * 32 + mt * 16 + (l >> 2);
                *(float2*)(ored + (size_t)r0 * 64 + col)       = make_float2(o[0], o[1]);
                *(float2*)(ored + (size_t)(r0 + 8) * 64 + col) = make_float2(o[2], o[3]);
            }
        }
    }
    __syncthreads();

    if (wn == 1) {
        #pragma unroll
        for (int mt = 0; mt < 2; ++mt) {
            int r0 = wm * 32 + mt * 16 + (l >> 2);
            float lt0 = lred[r0] + lred[128 + r0];
            float lt1 = lred[r0 + 8] + lred[128 + r0 + 8];
            float inv0 = (lt0 > 0.f) ? 1.f / lt0 : 0.f;
            float inv1 = (lt1 > 0.f) ? 1.f / lt1 : 0.f;
            size_t g0 = ((size_t)b * SS + qb * 128 + r0) * DD + h * 64;
            size_t g1 = g0 + (size_t)8 * DD;
            #pragma unroll
            for (int dt = 0; dt < 8; ++dt) {
                const float* o = oacc[mt][dt];
                int col = dt * 8 + 2 * (l & 3);
                float t0 = (o[0] + ored[(size_t)r0 * 64 + col])     * inv0;
                float t1 = (o[1] + ored[(size_t)r0 * 64 + col + 1]) * inv0;
                float t2 = (o[2] + ored[(size_t)(r0+8) * 64 + col])     * inv1;
                float t3 = (o[3] + ored[(size_t)(r0+8) * 64 + col + 1]) * inv1;
                *(uint32_t*)(ohp + g0 + col) = pk2(t0, t1);
                *(uint32_t*)(olp + g0 + col) = pk2(t0 - bfh(t0), t1 - bfh(t1));
                *(uint32_t*)(ohp + g1 + col) = pk2(t2, t3);
                *(uint32_t*)(olp + g1 + col) = pk2(t2 - bfh(t2), t3 - bfh(t3));
            }
        }
    }
}

// ---------------- host ----------------
extern "C" void kernel_launch(void* const* d_in, const int* in_sizes, int n_in,
                              void* d_out, int out_size)
{
    const float* x    = (const float*)d_in[0];
    const int*   mask = (const int*)d_in[1];
    const int*   pos  = (const int*)d_in[2];
    const float* Wq = (const float*)d_in[4];
    const float* bq = (const float*)d_in[5];
    const float* Wk = (const float*)d_in[6];
    const float* Wv = (const float*)d_in[7];
    const float* bv = (const float*)d_in[8];
    const float* Wo = (const float*)d_in[9];
    const float* bo = (const float*)d_in[10];
    float* out = (float*)d_out;

    __nv_bfloat16 *xh, *xl, *wqh, *wql, *wkh, *wkl, *wvh, *wvl, *woh, *wol;
    __nv_bfloat16 *qh, *ql, *kh, *kl, *vth, *vtl, *ah, *al;
    float *qf, *kf, *vf;
    cudaGetSymbolAddress((void**)&xh, xh_d);   cudaGetSymbolAddress((void**)&xl, xl_d);
    cudaGetSymbolAddress((void**)&wqh, Wqh_d); cudaGetSymbolAddress((void**)&wql, Wql_d);
    cudaGetSymbolAddress((void**)&wkh, Wkh_d); cudaGetSymbolAddress((void**)&wkl, Wkl_d);
    cudaGetSymbolAddress((void**)&wvh, Wvh_d); cudaGetSymbolAddress((void**)&wvl, Wvl_d);
    cudaGetSymbolAddress((void**)&woh, Woh_d); cudaGetSymbolAddress((void**)&wol, Wol_d);
    cudaGetSymbolAddress((void**)&qf, qf_d);   cudaGetSymbolAddress((void**)&kf, kf_d);
    cudaGetSymbolAddress((void**)&vf, vf_d);
    cudaGetSymbolAddress((void**)&qh, qh_d);   cudaGetSymbolAddress((void**)&ql, ql_d);
    cudaGetSymbolAddress((void**)&kh, kh_d);   cudaGetSymbolAddress((void**)&kl, kl_d);
    cudaGetSymbolAddress((void**)&vth, vth_d); cudaGetSymbolAddress((void**)&vtl, vtl_d);
    cudaGetSymbolAddress((void**)&ah, oh_d);   cudaGetSymbolAddress((void**)&al, ol_d);

    const long long OUTE = (long long)BB * SS * DD;
    const long long QKE  = (long long)BB * HH * SS * SS;
    float* qkp = ((long long)out_size >= OUTE + QKE) ? out + OUTE : (float*)0;

    SplitArgs sa;
    sa.in[0] = x;  sa.oh[0] = xh;  sa.ol[0] = xl;  sa.n4[0] = BB*SS*DD/4;
    sa.in[1] = Wq; sa.oh[1] = wqh; sa.ol[1] = wql; sa.n4[1] = DD*DD/4;
    sa.in[2] = Wk; sa.oh[2] = wkh; sa.ol[2] = wkl; sa.n4[2] = DD*DD/4;
    sa.in[3] = Wv; sa.oh[3] = wvh; sa.ol[3] = wvl; sa.n4[3] = DD*DD/4;
    sa.in[4] = Wo; sa.oh[4] = woh; sa.ol[4] = wol; sa.n4[4] = DD*DD/4;
    split_kernel<<<dim3((BB*SS*DD/4 + 255)/256, 5), 256>>>(sa);

    cudaFuncSetAttribute(qkv_gemm, cudaFuncAttributeMaxDynamicSharedMemorySize, G_SMEM);
    cudaFuncSetAttribute(out_gemm, cudaFuncAttributeMaxDynamicSharedMemorySize, G_SMEM);
    cudaFuncSetAttribute(attn_kernel, cudaFuncAttributeMaxDynamicSharedMemorySize, A_SMEM);

    qkv_gemm<<<dim3(24, (BB * SS) / 256), 256, G_SMEM>>>(
        xh, xl, wqh, wql, wkh, wkl, wvh, wvl, bq, bv, qf, kf, vf);

    rope_kernel<<<(BB*HH*SS*32)/256, 256>>>(qf, kf, pos, qh, ql, kh, kl);
    vtrans_kernel<<<dim3(SS/64, BB*HH), 256>>>(vf, vth, vtl);

    attn_kernel<<<dim3(SS/128, BB*HH), 256, A_SMEM>>>(qh, ql, kh, kl, vth, vtl,
                                                      mask, qkp, ah, al);

    out_gemm<<<dim3(DD/128, (BB * SS)/256), 256, G_SMEM>>>(ah, al, woh, wol, bo, out);
}

// round 14
// speedup vs baseline: 1.4713x; 1.4713x over previous
#include <cuda_runtime.h>
#include <cuda_bf16.h>
#include <stdint.h>
#include <math.h>

#define BB 2
#define SS 2048
#define DD 1024
#define HH 16
#define HD 64
#define NEG_INF (__int_as_float(0xff800000))

// ---------------- device scratch ----------------
__device__ __nv_bfloat16 xh_d[BB*SS*DD], xl_d[BB*SS*DD];
__device__ __nv_bfloat16 Wqh_d[DD*DD], Wql_d[DD*DD];
__device__ __nv_bfloat16 Wkh_d[DD*DD], Wkl_d[DD*DD];
__device__ __nv_bfloat16 Wvh_d[DD*DD], Wvl_d[DD*DD];
__device__ __nv_bfloat16 Woh_d[DD*DD], Wol_d[DD*DD];
__device__ float qf_d[BB*HH*SS*HD], kf_d[BB*HH*SS*HD], vf_d[BB*HH*SS*HD];
__device__ __nv_bfloat16 qh_d[BB*HH*SS*HD], ql_d[BB*HH*SS*HD];
__device__ __nv_bfloat16 kh_d[BB*HH*SS*HD], kl_d[BB*HH*SS*HD];
__device__ __nv_bfloat16 vth_d[BB*HH*SS*HD], vtl_d[BB*HH*SS*HD];
__device__ __nv_bfloat16 oh_d[BB*SS*DD], ol_d[BB*SS*DD];

// ---------------- helpers ----------------
__device__ __forceinline__ uint32_t smem_u32(const void* p) {
    uint32_t a;
    asm("{ .reg .u64 t; cvta.to.shared.u64 t, %1; cvt.u32.u64 %0, t; }" : "=r"(a) : "l"(p));
    return a;
}
#define SWZ(x) ((x) ^ (((x) >> 3) & 0x70))

__device__ __forceinline__ void cpa16(uint32_t dst, const void* src) {
    asm volatile("cp.async.cg.shared.global [%0], [%1], 16;" :: "r"(dst), "l"(src));
}
#define CP_COMMIT() asm volatile("cp.async.commit_group;" ::: "memory")
#define CP_WAIT2()  asm volatile("cp.async.wait_group 2;" ::: "memory")
#define CP_WAIT1()  asm volatile("cp.async.wait_group 1;" ::: "memory")
#define CP_WAIT0()  asm volatile("cp.async.wait_group 0;" ::: "memory")

__device__ __forceinline__ void ldm4(uint32_t r[4], uint32_t a) {
    asm volatile("ldmatrix.sync.aligned.m8n8.x4.shared.b16 {%0,%1,%2,%3}, [%4];"
        : "=r"(r[0]), "=r"(r[1]), "=r"(r[2]), "=r"(r[3]) : "r"(a));
}
__device__ __forceinline__ void mma_bf16(float* c, const uint32_t* a, const uint32_t* b) {
    asm volatile("mma.sync.aligned.m16n8k16.row.col.f32.bf16.bf16.f32 "
        "{%0,%1,%2,%3}, {%4,%5,%6,%7}, {%8,%9}, {%0,%1,%2,%3};"
        : "+f"(c[0]), "+f"(c[1]), "+f"(c[2]), "+f"(c[3])
        : "r"(a[0]), "r"(a[1]), "r"(a[2]), "r"(a[3]), "r"(b[0]), "r"(b[1]));
}
__device__ __forceinline__ uint32_t pk2(float a, float b) {
    __nv_bfloat162 t = __floats2bfloat162_rn(a, b);
    return *(uint32_t*)&t;
}
__device__ __forceinline__ float bfh(float v) {
    return __bfloat162float(__float2bfloat16_rn(v));
}
__device__ __forceinline__ void split1(float v, __nv_bfloat16& h, __nv_bfloat16& l) {
    h = __float2bfloat16_rn(v);
    l = __float2bfloat16_rn(v - __bfloat162float(h));
}

// ---------------- merged split kernel ----------------
struct SplitArgs {
    const float* in[5];
    __nv_bfloat16* oh[5];
    __nv_bfloat16* ol[5];
    int n4[5];
};
__global__ void split_kernel(SplitArgs a) {
    int w = blockIdx.y;
    int i = blockIdx.x * blockDim.x + threadIdx.x;
    if (i >= a.n4[w]) return;
    float4 v = ((const float4*)a.in[w])[i];
    uint2 hv, lv;
    hv.x = pk2(v.x, v.y); hv.y = pk2(v.z, v.w);
    lv.x = pk2(v.x - bfh(v.x), v.y - bfh(v.y));
    lv.y = pk2(v.z - bfh(v.z), v.w - bfh(v.w));
    ((uint2*)a.oh[w])[i] = hv;
    ((uint2*)a.ol[w])[i] = lv;
}

// ---------------- split-bf16 HMMA GEMM core, 3-stage cp.async, 128x128 tile ----------------
#define G_STG 65536
#define G_SMEM 196608

__device__ __forceinline__ void gemm_core(
    uint32_t sb, int tid, int m0, int n0,
    const __nv_bfloat16* __restrict__ Ah, const __nv_bfloat16* __restrict__ Al,
    const __nv_bfloat16* __restrict__ Bh, const __nv_bfloat16* __restrict__ Bl,
    float acc[4][4][4])
{
    const int wid = tid >> 5, l = tid & 31;
    const int wm = wid & 1, wn = wid >> 1;

    auto load_stage = [&](int c, int buf) {
        const int kt = c * 64;
        const uint32_t so = sb + buf * G_STG;
        #pragma unroll
        for (int t = 0; t < 4; ++t) {
            int e = tid + t * 256;
            int row = e >> 3, u = e & 7;
            uint32_t dst = SWZ((uint32_t)(row * 128 + u * 16));
            size_t ga = (size_t)(m0 + row) * DD + kt + u * 8;
            size_t gb = (size_t)(n0 + row) * DD + kt + u * 8;
            cpa16(so + dst,         Ah + ga);
            cpa16(so + 16384 + dst, Al + ga);
            cpa16(so + 32768 + dst, Bh + gb);
            cpa16(so + 49152 + dst, Bl + gb);
        }
    };

    load_stage(0, 0); CP_COMMIT();
    load_stage(1, 1); CP_COMMIT();

    for (int c = 0; c < 16; ++c) {
        if (c < 14)      { load_stage(c + 2, (c + 2) % 3); CP_COMMIT(); CP_WAIT2(); }
        else if (c == 14){ CP_WAIT1(); }
        else             { CP_WAIT0(); }
        __syncthreads();
        const uint32_t so = sb + (c % 3) * G_STG;
        #pragma unroll
        for (int ks = 0; ks < 4; ++ks) {
            uint32_t bh4[2][4], bl4[2][4];
            #pragma unroll
            for (int np = 0; np < 2; ++np) {
                int row = wn * 32 + np * 16 + ((l >> 4) & 1) * 8 + (l & 7);
                uint32_t off = SWZ((uint32_t)(row * 128 + ks * 32 + ((l >> 3) & 1) * 16));
                ldm4(bh4[np], so + 32768 + off);
                ldm4(bl4[np], so + 49152 + off);
            }
            #pragma unroll
            for (int mt = 0; mt < 4; ++mt) {
                int row = wm * 64 + mt * 16 + (l & 7) + ((l >> 3) & 1) * 8;
                uint32_t off = SWZ((uint32_t)(row * 128 + ks * 32 + ((l >> 4) & 1) * 16));
                uint32_t ah4[4], al4[4];
                ldm4(ah4, so + off);
                ldm4(al4, so + 16384 + off);
                #pragma unroll
                for (int nt = 0; nt < 4; ++nt) {
                    const uint32_t* bh = &bh4[nt >> 1][(nt & 1) * 2];
                    const uint32_t* bl = &bl4[nt >> 1][(nt & 1) * 2];
                    mma_bf16(acc[mt][nt], ah4, bh);
                    mma_bf16(acc[mt][nt], al4, bh);
                    mma_bf16(acc[mt][nt], ah4, bl);
                }
            }
        }
        __syncthreads();
    }
}

template<bool HEAD>
__device__ __forceinline__ void gemm_epilogue(
    int tid, int m0, int n0, const float* __restrict__ bias, float scale,
    float* __restrict__ C, float acc[4][4][4])
{
    const int wid = tid >> 5, l = tid & 31;
    const int wm = wid & 1, wn = wid >> 1;
    #pragma unroll
    for (int mt = 0; mt < 4; ++mt) {
        #pragma unroll
        for (int nt = 0; nt < 4; ++nt) {
            const float* cc = acc[mt][nt];
            int col = n0 + wn * 32 + nt * 8 + 2 * (l & 3);
            float b0 = bias ? bias[col] : 0.f;
            float b1 = bias ? bias[col + 1] : 0.f;
            int r0 = m0 + wm * 64 + mt * 16 + (l >> 2);
            #pragma unroll
            for (int hh = 0; hh < 2; ++hh) {
                int r = r0 + hh * 8;
                float2 w = {(cc[hh*2] + b0) * scale, (cc[hh*2+1] + b1) * scale};
                if (HEAD) {
                    int bb = r >> 11, s = r & (SS - 1);
                    int h = col >> 6, d = col & 63;
                    *(float2*)(C + (((size_t)(bb * HH + h)) * SS + s) * HD + d) = w;
                } else {
                    *(float2*)(C + (size_t)r * DD + col) = w;
                }
            }
        }
    }
}

// fused QKV projection: grid (24, 32); blockIdx.x>>3 selects Q/K/V
__global__ __launch_bounds__(256, 1)
void qkv_gemm(const __nv_bfloat16* __restrict__ Ah, const __nv_bfloat16* __restrict__ Al,
              const __nv_bfloat16* __restrict__ Qh, const __nv_bfloat16* __restrict__ Ql,
              const __nv_bfloat16* __restrict__ Kh, const __nv_bfloat16* __restrict__ Kl,
              const __nv_bfloat16* __restrict__ Vh, const __nv_bfloat16* __restrict__ Vl,
              const float* __restrict__ bq, const float* __restrict__ bv,
              float* __restrict__ qf, float* __restrict__ kf, float* __restrict__ vf)
{
    extern __shared__ char sm[];
    const uint32_t sb = smem_u32(sm);
    const int tid = threadIdx.x;
    const int which = blockIdx.x >> 3;
    const int n0 = (blockIdx.x & 7) * 128;
    const int m0 = blockIdx.y * 128;
    const float SC = 0.35355339059327373f;

    const __nv_bfloat16* Bh = (which == 0) ? Qh : (which == 1) ? Kh : Vh;
    const __nv_bfloat16* Bl = (which == 0) ? Ql : (which == 1) ? Kl : Vl;
    const float* bias = (which == 0) ? bq : (which == 1) ? (const float*)0 : bv;
    float scale = (which == 2) ? 1.f : SC;
    float* C = (which == 0) ? qf : (which == 1) ? kf : vf;

    float acc[4][4][4] = {};
    gemm_core(sb, tid, m0, n0, Ah, Al, Bh, Bl, acc);
    gemm_epilogue<true>(tid, m0, n0, bias, scale, C, acc);
}

// output projection
__global__ __launch_bounds__(256, 1)
void out_gemm(const __nv_bfloat16* __restrict__ Ah, const __nv_bfloat16* __restrict__ Al,
              const __nv_bfloat16* __restrict__ Bh, const __nv_bfloat16* __restrict__ Bl,
              const float* __restrict__ bias, float* __restrict__ C)
{
    extern __shared__ char sm[];
    const uint32_t sb = smem_u32(sm);
    const int tid = threadIdx.x;
    const int n0 = blockIdx.x * 128, m0 = blockIdx.y * 128;
    float acc[4][4][4] = {};
    gemm_core(sb, tid, m0, n0, Ah, Al, Bh, Bl, acc);
    gemm_epilogue<false>(tid, m0, n0, bias, 1.f, C, acc);
}

// ---------------- RoPE + split ----------------
__global__ void rope_kernel(const float* __restrict__ q, const float* __restrict__ k,
                            const int* __restrict__ pos,
                            __nv_bfloat16* __restrict__ qh, __nv_bfloat16* __restrict__ ql,
                            __nv_bfloat16* __restrict__ kh, __nv_bfloat16* __restrict__ kl)
{
    int idx = blockIdx.x * blockDim.x + threadIdx.x;
    if (idx >= BB * HH * SS * 32) return;
    int j = idx & 31;
    int s = (idx >> 5) & (SS - 1);
    int bh = idx >> 16;
    int b = bh >> 4;

    int p = pos[b * SS + s];
    float inv = expf(-(float)(2 * j) * (9.210340371976184f / 64.f));
    float ang = (float)p * inv;
    float sn, cs;
    sincosf(ang, &sn, &cs);

    size_t base = (size_t)bh * SS * HD + (size_t)s * HD + j;
    float q1 = q[base], q2 = q[base + 32];
    float k1 = k[base], k2 = k[base + 32];
    float qa = q1 * cs - q2 * sn, qb2 = q2 * cs + q1 * sn;
    float ka = k1 * cs - k2 * sn, kb2 = k2 * cs + k1 * sn;
    __nv_bfloat16 h, l;
    split1(qa, h, l);  qh[base] = h;      ql[base] = l;
    split1(qb2, h, l); qh[base + 32] = h; ql[base + 32] = l;
    split1(ka, h, l);  kh[base] = h;      kl[base] = l;
    split1(kb2, h, l); kh[base + 32] = h; kl[base + 32] = l;
}

// ---------------- V transpose + split ----------------
__global__ __launch_bounds__(256)
void vtrans_kernel(const float* __restrict__ v,
                   __nv_bfloat16* __restrict__ vth, __nv_bfloat16* __restrict__ vtl)
{
    __shared__ float ts[64][65];
    const int tid = threadIdx.x;
    const int s0 = blockIdx.x * 64;
    const int bh = blockIdx.y;
    #pragma unroll
    for (int t = 0; t < 16; ++t) {
        int e = tid + t * 256;
        int row = e >> 6, col = e & 63;
        ts[row][col] = v[((size_t)bh * SS + s0 + row) * HD + col];
    }
    __syncthreads();
    #pragma unroll
    for (int t = 0; t < 16; ++t) {
        int e = tid + t * 256;
        int d = e >> 6, s = e & 63;
        __nv_bfloat16 h, l;
        split1(ts[s][d], h, l);
        size_t a = ((size_t)bh * HD + d) * SS + s0 + s;
        vth[a] = h;
        vtl[a] = l;
    }
}

// ---------------- attention, R11 config: 2-stage cp.async, lb(256,2) ----------------
#define A_QH   0
#define A_QL   16384
#define A_ST   32768
#define A_STG  32768
#define A_ORED 32768
#define A_MK   98304
#define A_LRED 98816
#define A_SMEM 99840

__global__ __launch_bounds__(256, 2)
void attn_kernel(const __nv_bfloat16* __restrict__ qh, const __nv_bfloat16* __restrict__ ql,
                 const __nv_bfloat16* __restrict__ kh, const __nv_bfloat16* __restrict__ kl,
                 const __nv_bfloat16* __restrict__ vth, const __nv_bfloat16* __restrict__ vtl,
                 const int* __restrict__ mask,
                 float* __restrict__ qk_out,
                 __nv_bfloat16* __restrict__ ohp, __nv_bfloat16* __restrict__ olp)
{
    extern __shared__ char sm[];
    const uint32_t sb = smem_u32(sm);
    const int tid = threadIdx.x, wid = tid >> 5, l = tid & 31;
    const int wm = wid & 3, wn = wid >> 2;
    const int qb = blockIdx.x;
    const int bh = blockIdx.y;
    const int b = bh >> 4, h = bh & 15;
    int* mki = (int*)(sm + A_MK);
    float* lred = (float*)(sm + A_LRED);
    float* ored = (float*)(sm + A_ORED);

    #pragma unroll
    for (int t = 0; t < 4; ++t) {
        int e = tid + t * 256;
        int row = e >> 3, u = e & 7;
        uint32_t dst = SWZ((uint32_t)(row * 128 + u * 16));
        size_t src = ((size_t)bh * SS + qb * 128 + row) * HD + u * 8;
        *(uint4*)(sm + A_QH + dst) = *(const uint4*)(qh + src);
        *(uint4*)(sm + A_QL + dst) = *(const uint4*)(ql + src);
    }

    const int* mp = mask + b * SS;
    float* qkb = qk_out ? qk_out + ((size_t)bh * SS + (size_t)qb * 128) * SS : (float*)0;

    auto load_kv = [&](int kt, int buf) {
        const uint32_t so = sb + A_ST + buf * A_STG;
        #pragma unroll
        for (int t = 0; t < 2; ++t) {
            int e = tid + t * 256;
            int row = e >> 3, u = e & 7;
            uint32_t dst = SWZ((uint32_t)(row * 128 + u * 16));
            size_t ks = ((size_t)bh * SS + kt * 64 + row) * HD + u * 8;
            size_t vs = ((size_t)bh * HD + row) * SS + kt * 64 + u * 8;
            cpa16(so + dst,         kh  + ks);
            cpa16(so + 8192 + dst,  kl  + ks);
            cpa16(so + 16384 + dst, vth + vs);
            cpa16(so + 24576 + dst, vtl + vs);
        }
        if (tid < 16) cpa16(sb + A_MK + buf * 256 + tid * 16, mp + kt * 64 + tid * 4);
    };

    float oacc[2][8][4] = {};
    float lsum[2][2] = {};

    load_kv(0, 0);
    CP_COMMIT();

    for (int kt = 0; kt < 32; ++kt) {
        if (kt < 31) { load_kv(kt + 1, (kt + 1) & 1); CP_COMMIT(); CP_WAIT1(); }
        else         { CP_WAIT0(); }
        __syncthreads();
        const uint32_t so = sb + A_ST + (kt & 1) * A_STG;
        const int* mk = mki + (kt & 1) * 64;

        float sacc[2][4][4] = {};
        #pragma unroll
        for (int ks = 0; ks < 4; ++ks) {
            uint32_t kh4[2][4], kl4[2][4];
            #pragma unroll
            for (int np = 0; np < 2; ++np) {
                int row = wn * 32 + np * 16 + ((l >> 4) & 1) * 8 + (l & 7);
                uint32_t off = SWZ((uint32_t)(row * 128 + ks * 32 + ((l >> 3) & 1) * 16));
                ldm4(kh4[np], so + off);
                ldm4(kl4[np], so + 8192 + off);
            }
            #pragma unroll
            for (int mt = 0; mt < 2; ++mt) {
                int row = wm * 32 + mt * 16 + (l & 7) + ((l >> 3) & 1) * 8;
                uint32_t off = SWZ((uint32_t)(row * 128 + ks * 32 + ((l >> 4) & 1) * 16));
                uint32_t qh4[4], ql4[4];
                ldm4(qh4, sb + A_QH + off);
                ldm4(ql4, sb + A_QL + off);
                #pragma unroll
                for (int nt = 0; nt < 4; ++nt) {
                    const uint32_t* bhf = &kh4[nt >> 1][(nt & 1) * 2];
                    const uint32_t* blf = &kl4[nt >> 1][(nt & 1) * 2];
                    mma_bf16(sacc[mt][nt], qh4, bhf);
                    mma_bf16(sacc[mt][nt], ql4, bhf);
                    mma_bf16(sacc[mt][nt], qh4, blf);
                }
            }
        }

        uint32_t ph[2][2][4], pl[2][2][4];
        #pragma unroll
        for (int mt = 0; mt < 2; ++mt) {
            #pragma unroll
            for (int nt = 0; nt < 4; ++nt) {
                float* cc = sacc[mt][nt];
                int colg = wn * 32 + nt * 8 + 2 * (l & 3);
                int mv0 = mk[colg], mv1 = mk[colg + 1];
                int r0 = wm * 32 + mt * 16 + (l >> 2);
                if (qkb) {
                    float2 w0 = {mv0 ? cc[0] : NEG_INF, mv1 ? cc[1] : NEG_INF};
                    float2 w1 = {mv0 ? cc[2] : NEG_INF, mv1 ? cc[3] : NEG_INF};
                    __stcs((float2*)(qkb + (size_t)r0 * SS + kt * 64 + colg), w0);
                    __stcs((float2*)(qkb + (size_t)(r0 + 8) * SS + kt * 64 + colg), w1);
                }
                float p0 = mv0 ? __expf(cc[0]) : 0.f;
                float p1 = mv1 ? __expf(cc[1]) : 0.f;
                float p2 = mv0 ? __expf(cc[2]) : 0.f;
                float p3 = mv1 ? __expf(cc[3]) : 0.f;
                lsum[mt][0] += p0 + p1;
                lsum[mt][1] += p2 + p3;
                int t2 = nt >> 1, pos = nt & 1;
                ph[mt][t2][pos * 2]     = pk2(p0, p1);
                ph[mt][t2][pos * 2 + 1] = pk2(p2, p3);
                pl[mt][t2][pos * 2]     = pk2(p0 - bfh(p0), p1 - bfh(p1));
                pl[mt][t2][pos * 2 + 1] = pk2(p2 - bfh(p2), p3 - bfh(p3));
            }
        }

        #pragma unroll
        for (int ks = 0; ks < 2; ++ks) {
            #pragma unroll
            for (int dp = 0; dp < 4; ++dp) {
                int row = dp * 16 + ((l >> 4) & 1) * 8 + (l & 7);
                uint32_t off = SWZ((uint32_t)(row * 128 + wn * 64 + ks * 32 + ((l >> 3) & 1) * 16));
                uint32_t vh4[4], vl4[4];
                ldm4(vh4, so + 16384 + off);
                ldm4(vl4, so + 24576 + off);
                #pragma unroll
                for (int mt = 0; mt < 2; ++mt) {
                    #pragma unroll
                    for (int q2 = 0; q2 < 2; ++q2) {
                        float* o = oacc[mt][dp * 2 + q2];
                        const uint32_t* bhf = &vh4[q2 * 2];
                        const uint32_t* blf = &vl4[q2 * 2];
                        mma_bf16(o, ph[mt][ks], bhf);
                        mma_bf16(o, pl[mt][ks], bhf);
                        mma_bf16(o, ph[mt][ks], blf);
                    }
                }
            }
        }
        __syncthreads();
    }

    #pragma unroll
    for (int mt = 0; mt < 2; ++mt) {
        #pragma unroll
        for (int hf = 0; hf < 2; ++hf) {
            float v = lsum[mt][hf];
            v += __shfl_xor_sync(0xffffffffu, v, 1);
            v += __shfl_xor_sync(0xffffffffu, v, 2);
            int row = wm * 32 + mt * 16 + hf * 8 + (l >> 2);
            if ((l & 3) == 0) lred[wn * 128 + row] = v;
        }
    }
    if (wn == 0) {
        #pragma unroll
        for (int mt = 0; mt < 2; ++mt) {
            #pragma unroll
            for (int dt = 0; dt < 8; ++dt) {
                const float* o = oacc[mt][dt];
                int col = dt * 8 + 2 * (l & 3);
                int r0 = wm * 32 + mt * 16 + (l >> 2);
                *(float2*)(ored + (size_t)r0 * 64 + col)       = make_float2(o[0], o[1]);
                *(float2*)(ored + (size_t)(r0 + 8) * 64 + col) = make_float2(o[2], o[3]);
            }
        }
    }
    __syncthreads();

    if (wn == 1) {
        #pragma unroll
        for (int mt = 0; mt < 2; ++mt) {
            int r0 = wm * 32 + mt * 16 + (l >> 2);
            float lt0 = lred[r0] + lred[128 + r0];
            float lt1 = lred[r0 + 8] + lred[128 + r0 + 8];
            float inv0 = (lt0 > 0.f) ? 1.f / lt0 : 0.f;
            float inv1 = (lt1 > 0.f) ? 1.f / lt1 : 0.f;
            size_t g0 = ((size_t)b * SS + qb * 128 + r0) * DD + h * 64;
            size_t g1 = g0 + (size_t)8 * DD;
            #pragma unroll
            for (int dt = 0; dt < 8; ++dt) {
                const float* o = oacc[mt][dt];
                int col = dt * 8 + 2 * (l & 3);
                float t0 = (o[0] + ored[(size_t)r0 * 64 + col])     * inv0;
                float t1 = (o[1] + ored[(size_t)r0 * 64 + col + 1]) * inv0;
                float t2 = (o[2] + ored[(size_t)(r0+8) * 64 + col])     * inv1;
                float t3 = (o[3] + ored[(size_t)(r0+8) * 64 + col + 1]) * inv1;
                *(uint32_t*)(ohp + g0 + col) = pk2(t0, t1);
                *(uint32_t*)(olp + g0 + col) = pk2(t0 - bfh(t0), t1 - bfh(t1));
                *(uint32_t*)(ohp + g1 + col) = pk2(t2, t3);
                *(uint32_t*)(olp + g1 + col) = pk2(t2 - bfh(t2), t3 - bfh(t3));
            }
        }
    }
}

// ---------------- host ----------------
extern "C" void kernel_launch(void* const* d_in, const int* in_sizes, int n_in,
                              void* d_out, int out_size)
{
    const float* x    = (const float*)d_in[0];
    const int*   mask = (const int*)d_in[1];
    const int*   pos  = (const int*)d_in[2];
    const float* Wq = (const float*)d_in[4];
    const float* bq = (const float*)d_in[5];
    const float* Wk = (const float*)d_in[6];
    const float* Wv = (const float*)d_in[7];
    const float* bv = (const float*)d_in[8];
    const float* Wo = (const float*)d_in[9];
    const float* bo = (const float*)d_in[10];
    float* out = (float*)d_out;

    __nv_bfloat16 *xh, *xl, *wqh, *wql, *wkh, *wkl, *wvh, *wvl, *woh, *wol;
    __nv_bfloat16 *qh, *ql, *kh, *kl, *vth, *vtl, *ah, *al;
    float *qf, *kf, *vf;
    cudaGetSymbolAddress((void**)&xh, xh_d);   cudaGetSymbolAddress((void**)&xl, xl_d);
    cudaGetSymbolAddress((void**)&wqh, Wqh_d); cudaGetSymbolAddress((void**)&wql, Wql_d);
    cudaGetSymbolAddress((void**)&wkh, Wkh_d); cudaGetSymbolAddress((void**)&wkl, Wkl_d);
    cudaGetSymbolAddress((void**)&wvh, Wvh_d); cudaGetSymbolAddress((void**)&wvl, Wvl_d);
    cudaGetSymbolAddress((void**)&woh, Woh_d); cudaGetSymbolAddress((void**)&wol, Wol_d);
    cudaGetSymbolAddress((void**)&qf, qf_d);   cudaGetSymbolAddress((void**)&kf, kf_d);
    cudaGetSymbolAddress((void**)&vf, vf_d);
    cudaGetSymbolAddress((void**)&qh, qh_d);   cudaGetSymbolAddress((void**)&ql, ql_d);
    cudaGetSymbolAddress((void**)&kh, kh_d);   cudaGetSymbolAddress((void**)&kl, kl_d);
    cudaGetSymbolAddress((void**)&vth, vth_d); cudaGetSymbolAddress((void**)&vtl, vtl_d);
    cudaGetSymbolAddress((void**)&ah, oh_d);   cudaGetSymbolAddress((void**)&al, ol_d);

    const long long OUTE = (long long)BB * SS * DD;
    const long long QKE  = (long long)BB * HH * SS * SS;
    float* qkp = ((long long)out_size >= OUTE + QKE) ? out + OUTE : (float*)0;

    SplitArgs sa;
    sa.in[0] = x;  sa.oh[0] = xh;  sa.ol[0] = xl;  sa.n4[0] = BB*SS*DD/4;
    sa.in[1] = Wq; sa.oh[1] = wqh; sa.ol[1] = wql; sa.n4[1] = DD*DD/4;
    sa.in[2] = Wk; sa.oh[2] = wkh; sa.ol[2] = wkl; sa.n4[2] = DD*DD/4;
    sa.in[3] = Wv; sa.oh[3] = wvh; sa.ol[3] = wvl; sa.n4[3] = DD*DD/4;
    sa.in[4] = Wo; sa.oh[4] = woh; sa.ol[4] = wol; sa.n4[4] = DD*DD/4;
    split_kernel<<<dim3((BB*SS*DD/4 + 255)/256, 5), 256>>>(sa);

    cudaFuncSetAttribute(qkv_gemm, cudaFuncAttributeMaxDynamicSharedMemorySize, G_SMEM);
    cudaFuncSetAttribute(out_gemm, cudaFuncAttributeMaxDynamicSharedMemorySize, G_SMEM);
    cudaFuncSetAttribute(attn_kernel, cudaFuncAttributeMaxDynamicSharedMemorySize, A_SMEM);

    qkv_gemm<<<dim3(24, (BB * SS) / 128), 256, G_SMEM>>>(
        xh, xl, wqh, wql, wkh, wkl, wvh, wvl, bq, bv, qf, kf, vf);

    rope_kernel<<<(BB*HH*SS*32)/256, 256>>>(qf, kf, pos, qh, ql, kh, kl);
    vtrans_kernel<<<dim3(SS/64, BB*HH), 256>>>(vf, vth, vtl);

    attn_kernel<<<dim3(SS/128, BB*HH), 256, A_SMEM>>>(qh, ql, kh, kl, vth, vtl,
                                                      mask, qkp, ah, al);

    out_gemm<<<dim3(DD/128, (BB * SS)/128), 256, G_SMEM>>>(ah, al, woh, wol, bo, out);
}

// round 15
// speedup vs baseline: 2.0056x; 1.3631x over previous
#include <cuda_runtime.h>
#include <cuda_fp16.h>
#include <stdint.h>
#include <math.h>

#define BB 2
#define SS 2048
#define DD 1024
#define HH 16
#define HD 64
#define NEG_INF (__int_as_float(0xff800000))

// ---------------- device scratch ----------------
__device__ __half xh_d[BB*SS*DD], xl_d[BB*SS*DD];
__device__ __half Wqh_d[DD*DD], Wkh_d[DD*DD], Wvh_d[DD*DD], Woh_d[DD*DD];
__device__ float qf_d[BB*HH*SS*HD], kf_d[BB*HH*SS*HD], vf_d[BB*HH*SS*HD];
__device__ __half qh_d[BB*HH*SS*HD], ql_d[BB*HH*SS*HD];
__device__ __half kh_d[BB*HH*SS*HD];
__device__ __half vth_d[BB*HH*SS*HD], vtl_d[BB*HH*SS*HD];
__device__ __half oh_d[BB*SS*DD], ol_d[BB*SS*DD];

// ---------------- helpers ----------------
__device__ __forceinline__ uint32_t smem_u32(const void* p) {
    uint32_t a;
    asm("{ .reg .u64 t; cvta.to.shared.u64 t, %1; cvt.u32.u64 %0, t; }" : "=r"(a) : "l"(p));
    return a;
}
#define SWZ(x) ((x) ^ (((x) >> 3) & 0x70))

__device__ __forceinline__ void cpa16(uint32_t dst, const void* src) {
    asm volatile("cp.async.cg.shared.global [%0], [%1], 16;" :: "r"(dst), "l"(src));
}
#define CP_COMMIT() asm volatile("cp.async.commit_group;" ::: "memory")
#define CP_WAIT2()  asm volatile("cp.async.wait_group 2;" ::: "memory")
#define CP_WAIT1()  asm volatile("cp.async.wait_group 1;" ::: "memory")
#define CP_WAIT0()  asm volatile("cp.async.wait_group 0;" ::: "memory")

__device__ __forceinline__ void ldm4(uint32_t r[4], uint32_t a) {
    asm volatile("ldmatrix.sync.aligned.m8n8.x4.shared.b16 {%0,%1,%2,%3}, [%4];"
        : "=r"(r[0]), "=r"(r[1]), "=r"(r[2]), "=r"(r[3]) : "r"(a));
}
__device__ __forceinline__ void mma_f16(float* c, const uint32_t* a, const uint32_t* b) {
    asm volatile("mma.sync.aligned.m16n8k16.row.col.f32.f16.f16.f32 "
        "{%0,%1,%2,%3}, {%4,%5,%6,%7}, {%8,%9}, {%0,%1,%2,%3};"
        : "+f"(c[0]), "+f"(c[1]), "+f"(c[2]), "+f"(c[3])
        : "r"(a[0]), "r"(a[1]), "r"(a[2]), "r"(a[3]), "r"(b[0]), "r"(b[1]));
}
__device__ __forceinline__ uint32_t pk2(float a, float b) {
    __half2 t = __floats2half2_rn(a, b);
    return *(uint32_t*)&t;
}
__device__ __forceinline__ float hfh(float v) {    // value of fp16 hi part
    return __half2float(__float2half_rn(v));
}
__device__ __forceinline__ void split1(float v, __half& h, __half& l) {
    h = __float2half_rn(v);
    l = __float2half_rn(v - __half2float(h));
}

// ---------------- merged split kernel (2-term if ol != null, else 1-term) ----------------
struct SplitArgs {
    const float* in[5];
    __half* oh[5];
    __half* ol[5];
    int n4[5];
};
__global__ void split_kernel(SplitArgs a) {
    int w = blockIdx.y;
    int i = blockIdx.x * blockDim.x + threadIdx.x;
    if (i >= a.n4[w]) return;
    float4 v = ((const float4*)a.in[w])[i];
    uint2 hv;
    hv.x = pk2(v.x, v.y); hv.y = pk2(v.z, v.w);
    ((uint2*)a.oh[w])[i] = hv;
    if (a.ol[w]) {
        uint2 lv;
        lv.x = pk2(v.x - hfh(v.x), v.y - hfh(v.y));
        lv.y = pk2(v.z - hfh(v.z), v.w - hfh(v.w));
        ((uint2*)a.ol[w])[i] = lv;
    }
}

// ---------------- 2-term fp16 HMMA GEMM core, 3-stage cp.async, 128x128 tile ----------------
// stage (49152B): AH 0, AL 16384, BH 32768
#define G_STG 49152
#define G_SMEM 147456

__device__ __forceinline__ void gemm_core(
    uint32_t sb, int tid, int m0, int n0,
    const __half* __restrict__ Ah, const __half* __restrict__ Al,
    const __half* __restrict__ Bh,
    float acc[4][4][4])
{
    const int wid = tid >> 5, l = tid & 31;
    const int wm = wid & 1, wn = wid >> 1;

    auto load_stage = [&](int c, int buf) {
        const int kt = c * 64;
        const uint32_t so = sb + buf * G_STG;
        #pragma unroll
        for (int t = 0; t < 4; ++t) {
            int e = tid + t * 256;
            int row = e >> 3, u = e & 7;
            uint32_t dst = SWZ((uint32_t)(row * 128 + u * 16));
            size_t ga = (size_t)(m0 + row) * DD + kt + u * 8;
            size_t gb = (size_t)(n0 + row) * DD + kt + u * 8;
            cpa16(so + dst,         Ah + ga);
            cpa16(so + 16384 + dst, Al + ga);
            cpa16(so + 32768 + dst, Bh + gb);
        }
    };

    load_stage(0, 0); CP_COMMIT();
    load_stage(1, 1); CP_COMMIT();

    for (int c = 0; c < 16; ++c) {
        if (c < 14)      { load_stage(c + 2, (c + 2) % 3); CP_COMMIT(); CP_WAIT2(); }
        else if (c == 14){ CP_WAIT1(); }
        else             { CP_WAIT0(); }
        __syncthreads();
        const uint32_t so = sb + (c % 3) * G_STG;
        #pragma unroll
        for (int ks = 0; ks < 4; ++ks) {
            uint32_t bh4[2][4];
            #pragma unroll
            for (int np = 0; np < 2; ++np) {
                int row = wn * 32 + np * 16 + ((l >> 4) & 1) * 8 + (l & 7);
                uint32_t off = SWZ((uint32_t)(row * 128 + ks * 32 + ((l >> 3) & 1) * 16));
                ldm4(bh4[np], so + 32768 + off);
            }
            #pragma unroll
            for (int mt = 0; mt < 4; ++mt) {
                int row = wm * 64 + mt * 16 + (l & 7) + ((l >> 3) & 1) * 8;
                uint32_t off = SWZ((uint32_t)(row * 128 + ks * 32 + ((l >> 4) & 1) * 16));
                uint32_t ah4[4], al4[4];
                ldm4(ah4, so + off);
                ldm4(al4, so + 16384 + off);
                #pragma unroll
                for (int nt = 0; nt < 4; ++nt) {
                    const uint32_t* bh = &bh4[nt >> 1][(nt & 1) * 2];
                    mma_f16(acc[mt][nt], ah4, bh);
                    mma_f16(acc[mt][nt], al4, bh);
                }
            }
        }
        __syncthreads();
    }
}

template<bool HEAD>
__device__ __forceinline__ void gemm_epilogue(
    int tid, int m0, int n0, const float* __restrict__ bias, float scale,
    float* __restrict__ C, float acc[4][4][4])
{
    const int wid = tid >> 5, l = tid & 31;
    const int wm = wid & 1, wn = wid >> 1;
    #pragma unroll
    for (int mt = 0; mt < 4; ++mt) {
        #pragma unroll
        for (int nt = 0; nt < 4; ++nt) {
            const float* cc = acc[mt][nt];
            int col = n0 + wn * 32 + nt * 8 + 2 * (l & 3);
            float b0 = bias ? bias[col] : 0.f;
            float b1 = bias ? bias[col + 1] : 0.f;
            int r0 = m0 + wm * 64 + mt * 16 + (l >> 2);
            #pragma unroll
            for (int hh = 0; hh < 2; ++hh) {
                int r = r0 + hh * 8;
                float2 w = {(cc[hh*2] + b0) * scale, (cc[hh*2+1] + b1) * scale};
                if (HEAD) {
                    int bb = r >> 11, s = r & (SS - 1);
                    int h = col >> 6, d = col & 63;
                    *(float2*)(C + (((size_t)(bb * HH + h)) * SS + s) * HD + d) = w;
                } else {
                    *(float2*)(C + (size_t)r * DD + col) = w;
                }
            }
        }
    }
}

// fused QKV projection: grid (24, 32); blockIdx.x>>3 selects Q/K/V
__global__ __launch_bounds__(256, 1)
void qkv_gemm(const __half* __restrict__ Ah, const __half* __restrict__ Al,
              const __half* __restrict__ Qw, const __half* __restrict__ Kw,
              const __half* __restrict__ Vw,
              const float* __restrict__ bq, const float* __restrict__ bv,
              float* __restrict__ qf, float* __restrict__ kf, float* __restrict__ vf)
{
    extern __shared__ char sm[];
    const uint32_t sb = smem_u32(sm);
    const int tid = threadIdx.x;
    const int which = blockIdx.x >> 3;
    const int n0 = (blockIdx.x & 7) * 128;
    const int m0 = blockIdx.y * 128;
    const float SC = 0.35355339059327373f;

    const __half* Bh = (which == 0) ? Qw : (which == 1) ? Kw : Vw;
    const float* bias = (which == 0) ? bq : (which == 1) ? (const float*)0 : bv;
    float scale = (which == 2) ? 1.f : SC;
    float* C = (which == 0) ? qf : (which == 1) ? kf : vf;

    float acc[4][4][4] = {};
    gemm_core(sb, tid, m0, n0, Ah, Al, Bh, acc);
    gemm_epilogue<true>(tid, m0, n0, bias, scale, C, acc);
}

// output projection
__global__ __launch_bounds__(256, 1)
void out_gemm(const __half* __restrict__ Ah, const __half* __restrict__ Al,
              const __half* __restrict__ Bh,
              const float* __restrict__ bias, float* __restrict__ C)
{
    extern __shared__ char sm[];
    const uint32_t sb = smem_u32(sm);
    const int tid = threadIdx.x;
    const int n0 = blockIdx.x * 128, m0 = blockIdx.y * 128;
    float acc[4][4][4] = {};
    gemm_core(sb, tid, m0, n0, Ah, Al, Bh, acc);
    gemm_epilogue<false>(tid, m0, n0, bias, 1.f, C, acc);
}

// ---------------- RoPE + split (q 2-term, k 1-term) ----------------
__global__ void rope_kernel(const float* __restrict__ q, const float* __restrict__ k,
                            const int* __restrict__ pos,
                            __half* __restrict__ qh, __half* __restrict__ ql,
                            __half* __restrict__ kh)
{
    int idx = blockIdx.x * blockDim.x + threadIdx.x;
    if (idx >= BB * HH * SS * 32) return;
    int j = idx & 31;
    int s = (idx >> 5) & (SS - 1);
    int bh = idx >> 16;
    int b = bh >> 4;

    int p = pos[b * SS + s];
    float inv = expf(-(float)(2 * j) * (9.210340371976184f / 64.f));
    float ang = (float)p * inv;
    float sn, cs;
    sincosf(ang, &sn, &cs);

    size_t base = (size_t)bh * SS * HD + (size_t)s * HD + j;
    float q1 = q[base], q2 = q[base + 32];
    float k1 = k[base], k2 = k[base + 32];
    float qa = q1 * cs - q2 * sn, qb2 = q2 * cs + q1 * sn;
    float ka = k1 * cs - k2 * sn, kb2 = k2 * cs + k1 * sn;
    __half h, l;
    split1(qa, h, l);  qh[base] = h;      ql[base] = l;
    split1(qb2, h, l); qh[base + 32] = h; ql[base + 32] = l;
    kh[base]      = __float2half_rn(ka);
    kh[base + 32] = __float2half_rn(kb2);
}

// ---------------- V transpose + split (2-term) ----------------
__global__ __launch_bounds__(256)
void vtrans_kernel(const float* __restrict__ v,
                   __half* __restrict__ vth, __half* __restrict__ vtl)
{
    __shared__ float ts[64][65];
    const int tid = threadIdx.x;
    const int s0 = blockIdx.x * 64;
    const int bh = blockIdx.y;
    #pragma unroll
    for (int t = 0; t < 16; ++t) {
        int e = tid + t * 256;
        int row = e >> 6, col = e & 63;
        ts[row][col] = v[((size_t)bh * SS + s0 + row) * HD + col];
    }
    __syncthreads();
    #pragma unroll
    for (int t = 0; t < 16; ++t) {
        int e = tid + t * 256;
        int d = e >> 6, s = e & 63;
        __half h, l;
        split1(ts[s][d], h, l);
        size_t a = ((size_t)bh * HD + d) * SS + s0 + s;
        vth[a] = h;
        vtl[a] = l;
    }
}

// ---------------- attention: 2-stage cp.async, lb(256,2) ----------------
// smem: QH 0, QL 16384 | 2 stages at 32768 (stride 24576): KH 0, VTH 8192, VTL 16384
// ORED reuses 32768.. | MK 81920 (2x256B) | LRED 82432 (1KB) | total 83456
#define A_QH   0
#define A_QL   16384
#define A_ST   32768
#define A_STG  24576
#define A_ORED 32768
#define A_MK   81920
#define A_LRED 82432
#define A_SMEM 83456

__global__ __launch_bounds__(256, 2)
void attn_kernel(const __half* __restrict__ qh, const __half* __restrict__ ql,
                 const __half* __restrict__ kh,
                 const __half* __restrict__ vth, const __half* __restrict__ vtl,
                 const int* __restrict__ mask,
                 float* __restrict__ qk_out,
                 __half* __restrict__ ohp, __half* __restrict__ olp)
{
    extern __shared__ char sm[];
    const uint32_t sb = smem_u32(sm);
    const int tid = threadIdx.x, wid = tid >> 5, l = tid & 31;
    const int wm = wid & 3, wn = wid >> 2;
    const int qb = blockIdx.x;
    const int bh = blockIdx.y;
    const int b = bh >> 4, h = bh & 15;
    int* mki = (int*)(sm + A_MK);
    float* lred = (float*)(sm + A_LRED);
    float* ored = (float*)(sm + A_ORED);

    #pragma unroll
    for (int t = 0; t < 4; ++t) {
        int e = tid + t * 256;
        int row = e >> 3, u = e & 7;
        uint32_t dst = SWZ((uint32_t)(row * 128 + u * 16));
        size_t src = ((size_t)bh * SS + qb * 128 + row) * HD + u * 8;
        *(uint4*)(sm + A_QH + dst) = *(const uint4*)(qh + src);
        *(uint4*)(sm + A_QL + dst) = *(const uint4*)(ql + src);
    }

    const int* mp = mask + b * SS;
    float* qkb = qk_out ? qk_out + ((size_t)bh * SS + (size_t)qb * 128) * SS : (float*)0;

    auto load_kv = [&](int kt, int buf) {
        const uint32_t so = sb + A_ST + buf * A_STG;
        #pragma unroll
        for (int t = 0; t < 2; ++t) {
            int e = tid + t * 256;
            int row = e >> 3, u = e & 7;
            uint32_t dst = SWZ((uint32_t)(row * 128 + u * 16));
            size_t ks = ((size_t)bh * SS + kt * 64 + row) * HD + u * 8;
            size_t vs = ((size_t)bh * HD + row) * SS + kt * 64 + u * 8;
            cpa16(so + dst,         kh  + ks);
            cpa16(so + 8192 + dst,  vth + vs);
            cpa16(so + 16384 + dst, vtl + vs);
        }
        if (tid < 16) cpa16(sb + A_MK + buf * 256 + tid * 16, mp + kt * 64 + tid * 4);
    };

    float oacc[2][8][4] = {};
    float lsum[2][2] = {};

    load_kv(0, 0);
    CP_COMMIT();

    for (int kt = 0; kt < 32; ++kt) {
        if (kt < 31) { load_kv(kt + 1, (kt + 1) & 1); CP_COMMIT(); CP_WAIT1(); }
        else         { CP_WAIT0(); }
        __syncthreads();
        const uint32_t so = sb + A_ST + (kt & 1) * A_STG;
        const int* mk = mki + (kt & 1) * 64;

        // ---- S = Q K^T (Q 2-term, K 1-term) ----
        float sacc[2][4][4] = {};
        #pragma unroll
        for (int ks = 0; ks < 4; ++ks) {
            uint32_t kh4[2][4];
            #pragma unroll
            for (int np = 0; np < 2; ++np) {
                int row = wn * 32 + np * 16 + ((l >> 4) & 1) * 8 + (l & 7);
                uint32_t off = SWZ((uint32_t)(row * 128 + ks * 32 + ((l >> 3) & 1) * 16));
                ldm4(kh4[np], so + off);
            }
            #pragma unroll
            for (int mt = 0; mt < 2; ++mt) {
                int row = wm * 32 + mt * 16 + (l & 7) + ((l >> 3) & 1) * 8;
                uint32_t off = SWZ((uint32_t)(row * 128 + ks * 32 + ((l >> 4) & 1) * 16));
                uint32_t qh4[4], ql4[4];
                ldm4(qh4, sb + A_QH + off);
                ldm4(ql4, sb + A_QL + off);
                #pragma unroll
                for (int nt = 0; nt < 4; ++nt) {
                    const uint32_t* bhf = &kh4[nt >> 1][(nt & 1) * 2];
                    mma_f16(sacc[mt][nt], qh4, bhf);
                    mma_f16(sacc[mt][nt], ql4, bhf);
                }
            }
        }

        // ---- mask + raw logits out + exp + pack P (single fp16) ----
        uint32_t ph[2][2][4];
        #pragma unroll
        for (int mt = 0; mt < 2; ++mt) {
            #pragma unroll
            for (int nt = 0; nt < 4; ++nt) {
                float* cc = sacc[mt][nt];
                int colg = wn * 32 + nt * 8 + 2 * (l & 3);
                int mv0 = mk[colg], mv1 = mk[colg + 1];
                int r0 = wm * 32 + mt * 16 + (l >> 2);
                if (qkb) {
                    float2 w0 = {mv0 ? cc[0] : NEG_INF, mv1 ? cc[1] : NEG_INF};
                    float2 w1 = {mv0 ? cc[2] : NEG_INF, mv1 ? cc[3] : NEG_INF};
                    __stcs((float2*)(qkb + (size_t)r0 * SS + kt * 64 + colg), w0);
                    __stcs((float2*)(qkb + (size_t)(r0 + 8) * SS + kt * 64 + colg), w1);
                }
                float p0 = mv0 ? __expf(cc[0]) : 0.f;
                float p1 = mv1 ? __expf(cc[1]) : 0.f;
                float p2 = mv0 ? __expf(cc[2]) : 0.f;
                float p3 = mv1 ? __expf(cc[3]) : 0.f;
                lsum[mt][0] += p0 + p1;
                lsum[mt][1] += p2 + p3;
                int t2 = nt >> 1, pos = nt & 1;
                ph[mt][t2][pos * 2]     = pk2(p0, p1);
                ph[mt][t2][pos * 2 + 1] = pk2(p2, p3);
            }
        }

        // ---- O += P V (P 1-term, V 2-term) ----
        #pragma unroll
        for (int ks = 0; ks < 2; ++ks) {
            #pragma unroll
            for (int dp = 0; dp < 4; ++dp) {
                int row = dp * 16 + ((l >> 4) & 1) * 8 + (l & 7);
                uint32_t off = SWZ((uint32_t)(row * 128 + wn * 64 + ks * 32 + ((l >> 3) & 1) * 16));
                uint32_t vh4[4], vl4[4];
                ldm4(vh4, so + 8192 + off);
                ldm4(vl4, so + 16384 + off);
                #pragma unroll
                for (int mt = 0; mt < 2; ++mt) {
                    #pragma unroll
                    for (int q2 = 0; q2 < 2; ++q2) {
                        float* o = oacc[mt][dp * 2 + q2];
                        mma_f16(o, ph[mt][ks], &vh4[q2 * 2]);
                        mma_f16(o, ph[mt][ks], &vl4[q2 * 2]);
                    }
                }
            }
        }
        __syncthreads();
    }

    #pragma unroll
    for (int mt = 0; mt < 2; ++mt) {
        #pragma unroll
        for (int hf = 0; hf < 2; ++hf) {
            float v = lsum[mt][hf];
            v += __shfl_xor_sync(0xffffffffu, v, 1);
            v += __shfl_xor_sync(0xffffffffu, v, 2);
            int row = wm * 32 + mt * 16 + hf * 8 + (l >> 2);
            if ((l & 3) == 0) lred[wn * 128 + row] = v;
        }
    }
    if (wn == 0) {
        #pragma unroll
        for (int mt = 0; mt < 2; ++mt) {
            #pragma unroll
            for (int dt = 0; dt < 8; ++dt) {
                const float* o = oacc[mt][dt];
                int col = dt * 8 + 2 * (l & 3);
                int r0 = wm * 32 + mt * 16 + (l >> 2);
                *(float2*)(ored + (size_t)r0 * 64 + col)       = make_float2(o[0], o[1]);
                *(float2*)(ored + (size_t)(r0 + 8) * 64 + col) = make_float2(o[2], o[3]);
            }
        }
    }
    __syncthreads();

    if (wn == 1) {
        #pragma unroll
        for (int mt = 0; mt < 2; ++mt) {
            int r0 = wm * 32 + mt * 16 + (l >> 2);
            float lt0 = lred[r0] + lred[128 + r0];
            float lt1 = lred[r0 + 8] + lred[128 + r0 + 8];
            float inv0 = (lt0 > 0.f) ? 1.f / lt0 : 0.f;
            float inv1 = (lt1 > 0.f) ? 1.f / lt1 : 0.f;
            size_t g0 = ((size_t)b * SS + qb * 128 + r0) * DD + h * 64;
            size_t g1 = g0 + (size_t)8 * DD;
            #pragma unroll
            for (int dt = 0; dt < 8; ++dt) {
                const float* o = oacc[mt][dt];
                int col = dt * 8 + 2 * (l & 3);
                float t0 = (o[0] + ored[(size_t)r0 * 64 + col])     * inv0;
                float t1 = (o[1] + ored[(size_t)r0 * 64 + col + 1]) * inv0;
                float t2 = (o[2] + ored[(size_t)(r0+8) * 64 + col])     * inv1;
                float t3 = (o[3] + ored[(size_t)(r0+8) * 64 + col + 1]) * inv1;
                *(uint32_t*)(ohp + g0 + col) = pk2(t0, t1);
                *(uint32_t*)(olp + g0 + col) = pk2(t0 - hfh(t0), t1 - hfh(t1));
                *(uint32_t*)(ohp + g1 + col) = pk2(t2, t3);
                *(uint32_t*)(olp + g1 + col) = pk2(t2 - hfh(t2), t3 - hfh(t3));
            }
        }
    }
}

// ---------------- host ----------------
extern "C" void kernel_launch(void* const* d_in, const int* in_sizes, int n_in,
                              void* d_out, int out_size)
{
    const float* x    = (const float*)d_in[0];
    const int*   mask = (const int*)d_in[1];
    const int*   pos  = (const int*)d_in[2];
    const float* Wq = (const float*)d_in[4];
    const float* bq = (const float*)d_in[5];
    const float* Wk = (const float*)d_in[6];
    const float* Wv = (const float*)d_in[7];
    const float* bv = (const float*)d_in[8];
    const float* Wo = (const float*)d_in[9];
    const float* bo = (const float*)d_in[10];
    float* out = (float*)d_out;

    __half *xh, *xl, *wqh, *wkh, *wvh, *woh;
    __half *qh, *ql, *kh, *vth, *vtl, *ah, *al;
    float *qf, *kf, *vf;
    cudaGetSymbolAddress((void**)&xh, xh_d);   cudaGetSymbolAddress((void**)&xl, xl_d);
    cudaGetSymbolAddress((void**)&wqh, Wqh_d); cudaGetSymbolAddress((void**)&wkh, Wkh_d);
    cudaGetSymbolAddress((void**)&wvh, Wvh_d); cudaGetSymbolAddress((void**)&woh, Woh_d);
    cudaGetSymbolAddress((void**)&qf, qf_d);   cudaGetSymbolAddress((void**)&kf, kf_d);
    cudaGetSymbolAddress((void**)&vf, vf_d);
    cudaGetSymbolAddress((void**)&qh, qh_d);   cudaGetSymbolAddress((void**)&ql, ql_d);
    cudaGetSymbolAddress((void**)&kh, kh_d);
    cudaGetSymbolAddress((void**)&vth, vth_d); cudaGetSymbolAddress((void**)&vtl, vtl_d);
    cudaGetSymbolAddress((void**)&ah, oh_d);   cudaGetSymbolAddress((void**)&al, ol_d);

    const long long OUTE = (long long)BB * SS * DD;
    const long long QKE  = (long long)BB * HH * SS * SS;
    float* qkp = ((long long)out_size >= OUTE + QKE) ? out + OUTE : (float*)0;

    SplitArgs sa;
    sa.in[0] = x;  sa.oh[0] = xh;  sa.ol[0] = xl;       sa.n4[0] = BB*SS*DD/4;
    sa.in[1] = Wq; sa.oh[1] = wqh; sa.ol[1] = (__half*)0; sa.n4[1] = DD*DD/4;
    sa.in[2] = Wk; sa.oh[2] = wkh; sa.ol[2] = (__half*)0; sa.n4[2] = DD*DD/4;
    sa.in[3] = Wv; sa.oh[3] = wvh; sa.ol[3] = (__half*)0; sa.n4[3] = DD*DD/4;
    sa.in[4] = Wo; sa.oh[4] = woh; sa.ol[4] = (__half*)0; sa.n4[4] = DD*DD/4;
    split_kernel<<<dim3((BB*SS*DD/4 + 255)/256, 5), 256>>>(sa);

    cudaFuncSetAttribute(qkv_gemm, cudaFuncAttributeMaxDynamicSharedMemorySize, G_SMEM);
    cudaFuncSetAttribute(out_gemm, cudaFuncAttributeMaxDynamicSharedMemorySize, G_SMEM);
    cudaFuncSetAttribute(attn_kernel, cudaFuncAttributeMaxDynamicSharedMemorySize, A_SMEM);

    qkv_gemm<<<dim3(24, (BB * SS) / 128), 256, G_SMEM>>>(
        xh, xl, wqh, wkh, wvh, bq, bv, qf, kf, vf);

    rope_kernel<<<(BB*HH*SS*32)/256, 256>>>(qf, kf, pos, qh, ql, kh);
    vtrans_kernel<<<dim3(SS/64, BB*HH), 256>>>(vf, vth, vtl);

    attn_kernel<<<dim3(SS/128, BB*HH), 256, A_SMEM>>>(qh, ql, kh, vth, vtl,
                                                      mask, qkp, ah, al);

    out_gemm<<<dim3(DD/128, (BB * SS)/128), 256, G_SMEM>>>(ah, al, woh, bo, out);
}

// round 16
// speedup vs baseline: 2.2472x; 1.1205x over previous
#include <cuda_runtime.h>
#include <cuda_fp16.h>
#include <stdint.h>
#include <math.h>

#define BB 2
#define SS 2048
#define DD 1024
#define HH 16
#define HD 64
#define NEG_INF (__int_as_float(0xff800000))

// ---------------- device scratch ----------------
__device__ __half xh_d[BB*SS*DD], xl_d[BB*SS*DD];
__device__ __half Wqh_d[DD*DD], Wkh_d[DD*DD], Wvh_d[DD*DD], Woh_d[DD*DD];
__device__ float qf_d[BB*HH*SS*HD], kf_d[BB*HH*SS*HD], vf_d[BB*HH*SS*HD];
__device__ __half qh_d[BB*HH*SS*HD], ql_d[BB*HH*SS*HD];
__device__ __half kh_d[BB*HH*SS*HD];
__device__ __half vth_d[BB*HH*SS*HD];
__device__ __half oh_d[BB*SS*DD];

// ---------------- helpers ----------------
__device__ __forceinline__ uint32_t smem_u32(const void* p) {
    uint32_t a;
    asm("{ .reg .u64 t; cvta.to.shared.u64 t, %1; cvt.u32.u64 %0, t; }" : "=r"(a) : "l"(p));
    return a;
}
#define SWZ(x) ((x) ^ (((x) >> 3) & 0x70))

__device__ __forceinline__ void cpa16(uint32_t dst, const void* src) {
    asm volatile("cp.async.cg.shared.global [%0], [%1], 16;" :: "r"(dst), "l"(src));
}
#define CP_COMMIT() asm volatile("cp.async.commit_group;" ::: "memory")
#define CP_WAIT2()  asm volatile("cp.async.wait_group 2;" ::: "memory")
#define CP_WAIT1()  asm volatile("cp.async.wait_group 1;" ::: "memory")
#define CP_WAIT0()  asm volatile("cp.async.wait_group 0;" ::: "memory")

__device__ __forceinline__ void ldm4(uint32_t r[4], uint32_t a) {
    asm volatile("ldmatrix.sync.aligned.m8n8.x4.shared.b16 {%0,%1,%2,%3}, [%4];"
        : "=r"(r[0]), "=r"(r[1]), "=r"(r[2]), "=r"(r[3]) : "r"(a));
}
__device__ __forceinline__ void mma_f16(float* c, const uint32_t* a, const uint32_t* b) {
    asm volatile("mma.sync.aligned.m16n8k16.row.col.f32.f16.f16.f32 "
        "{%0,%1,%2,%3}, {%4,%5,%6,%7}, {%8,%9}, {%0,%1,%2,%3};"
        : "+f"(c[0]), "+f"(c[1]), "+f"(c[2]), "+f"(c[3])
        : "r"(a[0]), "r"(a[1]), "r"(a[2]), "r"(a[3]), "r"(b[0]), "r"(b[1]));
}
__device__ __forceinline__ uint32_t pk2(float a, float b) {
    __half2 t = __floats2half2_rn(a, b);
    return *(uint32_t*)&t;
}
__device__ __forceinline__ float hfh(float v) {
    return __half2float(__float2half_rn(v));
}
__device__ __forceinline__ void split1(float v, __half& h, __half& l) {
    h = __float2half_rn(v);
    l = __float2half_rn(v - __half2float(h));
}

// ---------------- merged split kernel (2-term if ol != null, else 1-term) ----------------
struct SplitArgs {
    const float* in[5];
    __half* oh[5];
    __half* ol[5];
    int n4[5];
};
__global__ void split_kernel(SplitArgs a) {
    int w = blockIdx.y;
    int i = blockIdx.x * blockDim.x + threadIdx.x;
    if (i >= a.n4[w]) return;
    float4 v = ((const float4*)a.in[w])[i];
    uint2 hv;
    hv.x = pk2(v.x, v.y); hv.y = pk2(v.z, v.w);
    ((uint2*)a.oh[w])[i] = hv;
    if (a.ol[w]) {
        uint2 lv;
        lv.x = pk2(v.x - hfh(v.x), v.y - hfh(v.y));
        lv.y = pk2(v.z - hfh(v.z), v.w - hfh(v.w));
        ((uint2*)a.ol[w])[i] = lv;
    }
}

// ---------------- 2-term-A fp16 GEMM core, 3-stage cp.async, 128x128 tile ----------------
// stage (49152B): AH 0, AL 16384, BH 32768
#define G_STG 49152
#define G_SMEM 147456

__device__ __forceinline__ void gemm_core2(
    uint32_t sb, int tid, int m0, int n0,
    const __half* __restrict__ Ah, const __half* __restrict__ Al,
    const __half* __restrict__ Bh,
    float acc[4][4][4])
{
    const int wid = tid >> 5, l = tid & 31;
    const int wm = wid & 1, wn = wid >> 1;

    auto load_stage = [&](int c, int buf) {
        const int kt = c * 64;
        const uint32_t so = sb + buf * G_STG;
        #pragma unroll
        for (int t = 0; t < 4; ++t) {
            int e = tid + t * 256;
            int row = e >> 3, u = e & 7;
            uint32_t dst = SWZ((uint32_t)(row * 128 + u * 16));
            size_t ga = (size_t)(m0 + row) * DD + kt + u * 8;
            size_t gb = (size_t)(n0 + row) * DD + kt + u * 8;
            cpa16(so + dst,         Ah + ga);
            cpa16(so + 16384 + dst, Al + ga);
            cpa16(so + 32768 + dst, Bh + gb);
        }
    };

    load_stage(0, 0); CP_COMMIT();
    load_stage(1, 1); CP_COMMIT();

    for (int c = 0; c < 16; ++c) {
        if (c < 14)      { load_stage(c + 2, (c + 2) % 3); CP_COMMIT(); CP_WAIT2(); }
        else if (c == 14){ CP_WAIT1(); }
        else             { CP_WAIT0(); }
        __syncthreads();
        const uint32_t so = sb + (c % 3) * G_STG;
        #pragma unroll
        for (int ks = 0; ks < 4; ++ks) {
            uint32_t bh4[2][4];
            #pragma unroll
            for (int np = 0; np < 2; ++np) {
                int row = wn * 32 + np * 16 + ((l >> 4) & 1) * 8 + (l & 7);
                uint32_t off = SWZ((uint32_t)(row * 128 + ks * 32 + ((l >> 3) & 1) * 16));
                ldm4(bh4[np], so + 32768 + off);
            }
            #pragma unroll
            for (int mt = 0; mt < 4; ++mt) {
                int row = wm * 64 + mt * 16 + (l & 7) + ((l >> 3) & 1) * 8;
                uint32_t off = SWZ((uint32_t)(row * 128 + ks * 32 + ((l >> 4) & 1) * 16));
                uint32_t ah4[4], al4[4];
                ldm4(ah4, so + off);
                ldm4(al4, so + 16384 + off);
                #pragma unroll
                for (int nt = 0; nt < 4; ++nt) {
                    const uint32_t* bh = &bh4[nt >> 1][(nt & 1) * 2];
                    mma_f16(acc[mt][nt], ah4, bh);
                    mma_f16(acc[mt][nt], al4, bh);
                }
            }
        }
        __syncthreads();
    }
}

// ---------------- 1-term-A fp16 GEMM core, 3-stage, 128x128 tile ----------------
// stage (32768B): AH 0, BH 16384
#define G1_STG 32768
#define G1_SMEM 98304

__device__ __forceinline__ void gemm_core1(
    uint32_t sb, int tid, int m0, int n0,
    const __half* __restrict__ Ah, const __half* __restrict__ Bh,
    float acc[4][4][4])
{
    const int wid = tid >> 5, l = tid & 31;
    const int wm = wid & 1, wn = wid >> 1;

    auto load_stage = [&](int c, int buf) {
        const int kt = c * 64;
        const uint32_t so = sb + buf * G1_STG;
        #pragma unroll
        for (int t = 0; t < 4; ++t) {
            int e = tid + t * 256;
            int row = e >> 3, u = e & 7;
            uint32_t dst = SWZ((uint32_t)(row * 128 + u * 16));
            size_t ga = (size_t)(m0 + row) * DD + kt + u * 8;
            size_t gb = (size_t)(n0 + row) * DD + kt + u * 8;
            cpa16(so + dst,         Ah + ga);
            cpa16(so + 16384 + dst, Bh + gb);
        }
    };

    load_stage(0, 0); CP_COMMIT();
    load_stage(1, 1); CP_COMMIT();

    for (int c = 0; c < 16; ++c) {
        if (c < 14)      { load_stage(c + 2, (c + 2) % 3); CP_COMMIT(); CP_WAIT2(); }
        else if (c == 14){ CP_WAIT1(); }
        else             { CP_WAIT0(); }
        __syncthreads();
        const uint32_t so = sb + (c % 3) * G1_STG;
        #pragma unroll
        for (int ks = 0; ks < 4; ++ks) {
            uint32_t bh4[2][4];
            #pragma unroll
            for (int np = 0; np < 2; ++np) {
                int row = wn * 32 + np * 16 + ((l >> 4) & 1) * 8 + (l & 7);
                uint32_t off = SWZ((uint32_t)(row * 128 + ks * 32 + ((l >> 3) & 1) * 16));
                ldm4(bh4[np], so + 16384 + off);
            }
            #pragma unroll
            for (int mt = 0; mt < 4; ++mt) {
                int row = wm * 64 + mt * 16 + (l & 7) + ((l >> 3) & 1) * 8;
                uint32_t off = SWZ((uint32_t)(row * 128 + ks * 32 + ((l >> 4) & 1) * 16));
                uint32_t ah4[4];
                ldm4(ah4, so + off);
                #pragma unroll
                for (int nt = 0; nt < 4; ++nt) {
                    const uint32_t* bh = &bh4[nt >> 1][(nt & 1) * 2];
                    mma_f16(acc[mt][nt], ah4, bh);
                }
            }
        }
        __syncthreads();
    }
}

template<bool HEAD>
__device__ __forceinline__ void gemm_epilogue(
    int tid, int m0, int n0, const float* __restrict__ bias, float scale,
    float* __restrict__ C, float acc[4][4][4])
{
    const int wid = tid >> 5, l = tid & 31;
    const int wm = wid & 1, wn = wid >> 1;
    #pragma unroll
    for (int mt = 0; mt < 4; ++mt) {
        #pragma unroll
        for (int nt = 0; nt < 4; ++nt) {
            const float* cc = acc[mt][nt];
            int col = n0 + wn * 32 + nt * 8 + 2 * (l & 3);
            float b0 = bias ? bias[col] : 0.f;
            float b1 = bias ? bias[col + 1] : 0.f;
            int r0 = m0 + wm * 64 + mt * 16 + (l >> 2);
            #pragma unroll
            for (int hh = 0; hh < 2; ++hh) {
                int r = r0 + hh * 8;
                float2 w = {(cc[hh*2] + b0) * scale, (cc[hh*2+1] + b1) * scale};
                if (HEAD) {
                    int bb = r >> 11, s = r & (SS - 1);
                    int h = col >> 6, d = col & 63;
                    *(float2*)(C + (((size_t)(bb * HH + h)) * SS + s) * HD + d) = w;
                } else {
                    *(float2*)(C + (size_t)r * DD + col) = w;
                }
            }
        }
    }
}

// fused QKV projection: grid (24, 32); blockIdx.x>>3 selects Q/K/V
__global__ __launch_bounds__(256, 1)
void qkv_gemm(const __half* __restrict__ Ah, const __half* __restrict__ Al,
              const __half* __restrict__ Qw, const __half* __restrict__ Kw,
              const __half* __restrict__ Vw,
              const float* __restrict__ bq, const float* __restrict__ bv,
              float* __restrict__ qf, float* __restrict__ kf, float* __restrict__ vf)
{
    extern __shared__ char sm[];
    const uint32_t sb = smem_u32(sm);
    const int tid = threadIdx.x;
    const int which = blockIdx.x >> 3;
    const int n0 = (blockIdx.x & 7) * 128;
    const int m0 = blockIdx.y * 128;
    const float SC = 0.35355339059327373f;

    const __half* Bh = (which == 0) ? Qw : (which == 1) ? Kw : Vw;
    const float* bias = (which == 0) ? bq : (which == 1) ? (const float*)0 : bv;
    float scale = (which == 2) ? 1.f : SC;
    float* C = (which == 0) ? qf : (which == 1) ? kf : vf;

    float acc[4][4][4] = {};
    gemm_core2(sb, tid, m0, n0, Ah, Al, Bh, acc);
    gemm_epilogue<true>(tid, m0, n0, bias, scale, C, acc);
}

// output projection (1-term A)
__global__ __launch_bounds__(256, 1)
void out_gemm(const __half* __restrict__ Ah, const __half* __restrict__ Bh,
              const float* __restrict__ bias, float* __restrict__ C)
{
    extern __shared__ char sm[];
    const uint32_t sb = smem_u32(sm);
    const int tid = threadIdx.x;
    const int n0 = blockIdx.x * 128, m0 = blockIdx.y * 128;
    float acc[4][4][4] = {};
    gemm_core1(sb, tid, m0, n0, Ah, Bh, acc);
    gemm_epilogue<false>(tid, m0, n0, bias, 1.f, C, acc);
}

// ---------------- RoPE + split (q 2-term, k 1-term) ----------------
__global__ void rope_kernel(const float* __restrict__ q, const float* __restrict__ k,
                            const int* __restrict__ pos,
                            __half* __restrict__ qh, __half* __restrict__ ql,
                            __half* __restrict__ kh)
{
    int idx = blockIdx.x * blockDim.x + threadIdx.x;
    if (idx >= BB * HH * SS * 32) return;
    int j = idx & 31;
    int s = (idx >> 5) & (SS - 1);
    int bh = idx >> 16;
    int b = bh >> 4;

    int p = pos[b * SS + s];
    float inv = expf(-(float)(2 * j) * (9.210340371976184f / 64.f));
    float ang = (float)p * inv;
    float sn, cs;
    sincosf(ang, &sn, &cs);

    size_t base = (size_t)bh * SS * HD + (size_t)s * HD + j;
    float q1 = q[base], q2 = q[base + 32];
    float k1 = k[base], k2 = k[base + 32];
    float qa = q1 * cs - q2 * sn, qb2 = q2 * cs + q1 * sn;
    float ka = k1 * cs - k2 * sn, kb2 = k2 * cs + k1 * sn;
    __half h, l;
    split1(qa, h, l);  qh[base] = h;      ql[base] = l;
    split1(qb2, h, l); qh[base + 32] = h; ql[base + 32] = l;
    kh[base]      = __float2half_rn(ka);
    kh[base + 32] = __float2half_rn(kb2);
}

// ---------------- V transpose (1-term) ----------------
__global__ __launch_bounds__(256)
void vtrans_kernel(const float* __restrict__ v, __half* __restrict__ vth)
{
    __shared__ float ts[64][65];
    const int tid = threadIdx.x;
    const int s0 = blockIdx.x * 64;
    const int bh = blockIdx.y;
    #pragma unroll
    for (int t = 0; t < 16; ++t) {
        int e = tid + t * 256;
        int row = e >> 6, col = e & 63;
        ts[row][col] = v[((size_t)bh * SS + s0 + row) * HD + col];
    }
    __syncthreads();
    #pragma unroll
    for (int t = 0; t < 16; ++t) {
        int e = tid + t * 256;
        int d = e >> 6, s = e & 63;
        size_t a = ((size_t)bh * HD + d) * SS + s0 + s;
        vth[a] = __float2half_rn(ts[s][d]);
    }
}

// ---------------- attention: 2-stage cp.async, lb(256,2) ----------------
// smem: QH 0, QL 16384 | 2 stages at 32768 (stride 16384): KH 0, VTH 8192
// ORED reuses 32768..65536 | MK 65536 (2x256B) | LRED 66048 (1KB) | total 67072
#define A_QH   0
#define A_QL   16384
#define A_ST   32768
#define A_STG  16384
#define A_ORED 32768
#define A_MK   65536
#define A_LRED 66048
#define A_SMEM 67072

__global__ __launch_bounds__(256, 2)
void attn_kernel(const __half* __restrict__ qh, const __half* __restrict__ ql,
                 const __half* __restrict__ kh,
                 const __half* __restrict__ vth,
                 const int* __restrict__ mask,
                 float* __restrict__ qk_out,
                 __half* __restrict__ ohp)
{
    extern __shared__ char sm[];
    const uint32_t sb = smem_u32(sm);
    const int tid = threadIdx.x, wid = tid >> 5, l = tid & 31;
    const int wm = wid & 3, wn = wid >> 2;
    const int qb = blockIdx.x;
    const int bh = blockIdx.y;
    const int b = bh >> 4, h = bh & 15;
    int* mki = (int*)(sm + A_MK);
    float* lred = (float*)(sm + A_LRED);
    float* ored = (float*)(sm + A_ORED);

    #pragma unroll
    for (int t = 0; t < 4; ++t) {
        int e = tid + t * 256;
        int row = e >> 3, u = e & 7;
        uint32_t dst = SWZ((uint32_t)(row * 128 + u * 16));
        size_t src = ((size_t)bh * SS + qb * 128 + row) * HD + u * 8;
        *(uint4*)(sm + A_QH + dst) = *(const uint4*)(qh + src);
        *(uint4*)(sm + A_QL + dst) = *(const uint4*)(ql + src);
    }

    const int* mp = mask + b * SS;
    float* qkb = qk_out ? qk_out + ((size_t)bh * SS + (size_t)qb * 128) * SS : (float*)0;

    auto load_kv = [&](int kt, int buf) {
        const uint32_t so = sb + A_ST + buf * A_STG;
        #pragma unroll
        for (int t = 0; t < 2; ++t) {
            int e = tid + t * 256;
            int row = e >> 3, u = e & 7;
            uint32_t dst = SWZ((uint32_t)(row * 128 + u * 16));
            size_t ks = ((size_t)bh * SS + kt * 64 + row) * HD + u * 8;
            size_t vs = ((size_t)bh * HD + row) * SS + kt * 64 + u * 8;
            cpa16(so + dst,        kh  + ks);
            cpa16(so + 8192 + dst, vth + vs);
        }
        if (tid < 16) cpa16(sb + A_MK + buf * 256 + tid * 16, mp + kt * 64 + tid * 4);
    };

    float oacc[2][8][4] = {};
    float lsum[2][2] = {};

    load_kv(0, 0);
    CP_COMMIT();

    for (int kt = 0; kt < 32; ++kt) {
        if (kt < 31) { load_kv(kt + 1, (kt + 1) & 1); CP_COMMIT(); CP_WAIT1(); }
        else         { CP_WAIT0(); }
        __syncthreads();
        const uint32_t so = sb + A_ST + (kt & 1) * A_STG;
        const int* mk = mki + (kt & 1) * 64;

        // ---- S = Q K^T (Q 2-term, K 1-term) ----
        float sacc[2][4][4] = {};
        #pragma unroll
        for (int ks = 0; ks < 4; ++ks) {
            uint32_t kh4[2][4];
            #pragma unroll
            for (int np = 0; np < 2; ++np) {
                int row = wn * 32 + np * 16 + ((l >> 4) & 1) * 8 + (l & 7);
                uint32_t off = SWZ((uint32_t)(row * 128 + ks * 32 + ((l >> 3) & 1) * 16));
                ldm4(kh4[np], so + off);
            }
            #pragma unroll
            for (int mt = 0; mt < 2; ++mt) {
                int row = wm * 32 + mt * 16 + (l & 7) + ((l >> 3) & 1) * 8;
                uint32_t off = SWZ((uint32_t)(row * 128 + ks * 32 + ((l >> 4) & 1) * 16));
                uint32_t qh4[4], ql4[4];
                ldm4(qh4, sb + A_QH + off);
                ldm4(ql4, sb + A_QL + off);
                #pragma unroll
                for (int nt = 0; nt < 4; ++nt) {
                    const uint32_t* bhf = &kh4[nt >> 1][(nt & 1) * 2];
                    mma_f16(sacc[mt][nt], qh4, bhf);
                    mma_f16(sacc[mt][nt], ql4, bhf);
                }
            }
        }

        // ---- mask + raw logits out + exp + pack P (single fp16) ----
        uint32_t ph[2][2][4];
        #pragma unroll
        for (int mt = 0; mt < 2; ++mt) {
            #pragma unroll
            for (int nt = 0; nt < 4; ++nt) {
                float* cc = sacc[mt][nt];
                int colg = wn * 32 + nt * 8 + 2 * (l & 3);
                int mv0 = mk[colg], mv1 = mk[colg + 1];
                int r0 = wm * 32 + mt * 16 + (l >> 2);
                if (qkb) {
                    float2 w0 = {mv0 ? cc[0] : NEG_INF, mv1 ? cc[1] : NEG_INF};
                    float2 w1 = {mv0 ? cc[2] : NEG_INF, mv1 ? cc[3] : NEG_INF};
                    __stcs((float2*)(qkb + (size_t)r0 * SS + kt * 64 + colg), w0);
                    __stcs((float2*)(qkb + (size_t)(r0 + 8) * SS + kt * 64 + colg), w1);
                }
                float p0 = mv0 ? __expf(cc[0]) : 0.f;
                float p1 = mv1 ? __expf(cc[1]) : 0.f;
                float p2 = mv0 ? __expf(cc[2]) : 0.f;
                float p3 = mv1 ? __expf(cc[3]) : 0.f;
                lsum[mt][0] += p0 + p1;
                lsum[mt][1] += p2 + p3;
                int t2 = nt >> 1, pos = nt & 1;
                ph[mt][t2][pos * 2]     = pk2(p0, p1);
                ph[mt][t2][pos * 2 + 1] = pk2(p2, p3);
            }
        }

        // ---- O += P V (both 1-term) ----
        #pragma unroll
        for (int ks = 0; ks < 2; ++ks) {
            #pragma unroll
            for (int dp = 0; dp < 4; ++dp) {
                int row = dp * 16 + ((l >> 4) & 1) * 8 + (l & 7);
                uint32_t off = SWZ((uint32_t)(row * 128 + wn * 64 + ks * 32 + ((l >> 3) & 1) * 16));
                uint32_t vh4[4];
                ldm4(vh4, so + 8192 + off);
                #pragma unroll
                for (int mt = 0; mt < 2; ++mt) {
                    #pragma unroll
                    for (int q2 = 0; q2 < 2; ++q2) {
                        mma_f16(oacc[mt][dp * 2 + q2], ph[mt][ks], &vh4[q2 * 2]);
                    }
                }
            }
        }
        __syncthreads();
    }

    #pragma unroll
    for (int mt = 0; mt < 2; ++mt) {
        #pragma unroll
        for (int hf = 0; hf < 2; ++hf) {
            float v = lsum[mt][hf];
            v += __shfl_xor_sync(0xffffffffu, v, 1);
            v += __shfl_xor_sync(0xffffffffu, v, 2);
            int row = wm * 32 + mt * 16 + hf * 8 + (l >> 2);
            if ((l & 3) == 0) lred[wn * 128 + row] = v;
        }
    }
    if (wn == 0) {
        #pragma unroll
        for (int mt = 0; mt < 2; ++mt) {
            #pragma unroll
            for (int dt = 0; dt < 8; ++dt) {
                const float* o = oacc[mt][dt];
                int col = dt * 8 + 2 * (l & 3);
                int r0 = wm * 32 + mt * 16 + (l >> 2);
                *(float2*)(ored + (size_t)r0 * 64 + col)       = make_float2(o[0], o[1]);
                *(float2*)(ored + (size_t)(r0 + 8) * 64 + col) = make_float2(o[2], o[3]);
            }
        }
    }
    __syncthreads();

    if (wn == 1) {
        #pragma unroll
        for (int mt = 0; mt < 2; ++mt) {
            int r0 = wm * 32 + mt * 16 + (l >> 2);
            float lt0 = lred[r0] + lred[128 + r0];
            float lt1 = lred[r0 + 8] + lred[128 + r0 + 8];
            float inv0 = (lt0 > 0.f) ? 1.f / lt0 : 0.f;
            float inv1 = (lt1 > 0.f) ? 1.f / lt1 : 0.f;
            size_t g0 = ((size_t)b * SS + qb * 128 + r0) * DD + h * 64;
            size_t g1 = g0 + (size_t)8 * DD;
            #pragma unroll
            for (int dt = 0; dt < 8; ++dt) {
                const float* o = oacc[mt][dt];
                int col = dt * 8 + 2 * (l & 3);
                float t0 = (o[0] + ored[(size_t)r0 * 64 + col])     * inv0;
                float t1 = (o[1] + ored[(size_t)r0 * 64 + col + 1]) * inv0;
                float t2 = (o[2] + ored[(size_t)(r0+8) * 64 + col])     * inv1;
                float t3 = (o[3] + ored[(size_t)(r0+8) * 64 + col + 1]) * inv1;
                *(uint32_t*)(ohp + g0 + col) = pk2(t0, t1);
                *(uint32_t*)(ohp + g1 + col) = pk2(t2, t3);
            }
        }
    }
}

// ---------------- host ----------------
extern "C" void kernel_launch(void* const* d_in, const int* in_sizes, int n_in,
                              void* d_out, int out_size)
{
    const float* x    = (const float*)d_in[0];
    const int*   mask = (const int*)d_in[1];
    const int*   pos  = (const int*)d_in[2];
    const float* Wq = (const float*)d_in[4];
    const float* bq = (const float*)d_in[5];
    const float* Wk = (const float*)d_in[6];
    const float* Wv = (const float*)d_in[7];
    const float* bv = (const float*)d_in[8];
    const float* Wo = (const float*)d_in[9];
    const float* bo = (const float*)d_in[10];
    float* out = (float*)d_out;

    __half *xh, *xl, *wqh, *wkh, *wvh, *woh;
    __half *qh, *ql, *kh, *vth, *ah;
    float *qf, *kf, *vf;
    cudaGetSymbolAddress((void**)&xh, xh_d);   cudaGetSymbolAddress((void**)&xl, xl_d);
    cudaGetSymbolAddress((void**)&wqh, Wqh_d); cudaGetSymbolAddress((void**)&wkh, Wkh_d);
    cudaGetSymbolAddress((void**)&wvh, Wvh_d); cudaGetSymbolAddress((void**)&woh, Woh_d);
    cudaGetSymbolAddress((void**)&qf, qf_d);   cudaGetSymbolAddress((void**)&kf, kf_d);
    cudaGetSymbolAddress((void**)&vf, vf_d);
    cudaGetSymbolAddress((void**)&qh, qh_d);   cudaGetSymbolAddress((void**)&ql, ql_d);
    cudaGetSymbolAddress((void**)&kh, kh_d);
    cudaGetSymbolAddress((void**)&vth, vth_d);
    cudaGetSymbolAddress((void**)&ah, oh_d);

    const long long OUTE = (long long)BB * SS * DD;
    const long long QKE  = (long long)BB * HH * SS * SS;
    float* qkp = ((long long)out_size >= OUTE + QKE) ? out + OUTE : (float*)0;

    SplitArgs sa;
    sa.in[0] = x;  sa.oh[0] = xh;  sa.ol[0] = xl;         sa.n4[0] = BB*SS*DD/4;
    sa.in[1] = Wq; sa.oh[1] = wqh; sa.ol[1] = (__half*)0; sa.n4[1] = DD*DD/4;
    sa.in[2] = Wk; sa.oh[2] = wkh; sa.ol[2] = (__half*)0; sa.n4[2] = DD*DD/4;
    sa.in[3] = Wv; sa.oh[3] = wvh; sa.ol[3] = (__half*)0; sa.n4[3] = DD*DD/4;
    sa.in[4] = Wo; sa.oh[4] = woh; sa.ol[4] = (__half*)0; sa.n4[4] = DD*DD/4;
    split_kernel<<<dim3((BB*SS*DD/4 + 255)/256, 5), 256>>>(sa);

    cudaFuncSetAttribute(qkv_gemm, cudaFuncAttributeMaxDynamicSharedMemorySize, G_SMEM);
    cudaFuncSetAttribute(out_gemm, cudaFuncAttributeMaxDynamicSharedMemorySize, G1_SMEM);
    cudaFuncSetAttribute(attn_kernel, cudaFuncAttributeMaxDynamicSharedMemorySize, A_SMEM);

    qkv_gemm<<<dim3(24, (BB * SS) / 128), 256, G_SMEM>>>(
        xh, xl, wqh, wkh, wvh, bq, bv, qf, kf, vf);

    rope_kernel<<<(BB*HH*SS*32)/256, 256>>>(qf, kf, pos, qh, ql, kh);
    vtrans_kernel<<<dim3(SS/64, BB*HH), 256>>>(vf, vth);

    attn_kernel<<<dim3(SS/128, BB*HH), 256, A_SMEM>>>(qh, ql, kh, vth,
                                                      mask, qkp, ah);

    out_gemm<<<dim3(DD/128, (BB * SS)/128), 256, G1_SMEM>>>(ah, woh, bo, out);
}